// round 1
// baseline (speedup 1.0000x reference)
#include <cuda_runtime.h>
#include <cuda_bf16.h>

// ---------------------------------------------------------------------------
// TransformerConv: N=100000 nodes, E=1600000 edges, IN=128, H=4, C=32, ED=16
//
// Pipeline:
//   1) proj_kernel : q,k,v,skip = x @ {Wq,Wk,Wv,Wskip} + bias  (FFMA2 fp32 GEMM)
//   2) gfold_kernel: g[n,h,d] = sum_c q[n,h,c] * We[d, h*32+c]  (folds edge
//      feature projection into a per-node 64-vector => per-edge cost 16 FMA/head)
//   3) zero_counts / fill_buckets: bucket edges by destination node
//   4) agg_kernel  : warp-per-dst-node softmax aggregation + gated skip, fused
// ---------------------------------------------------------------------------

#define MAXN 100096
#define MAXE 1600000
#define BCAP 96   // per-node bucket capacity (Poisson(16) max ~36; 96 is safe)

__device__ float d_qbuf[MAXN * 128];
__device__ float d_kbuf[MAXN * 128];
__device__ float d_vbuf[MAXN * 128];
__device__ float d_sbuf[MAXN * 128];
__device__ float d_gbuf[MAXN * 64];
__device__ int   d_count[MAXN];
__device__ int   d_bucket[MAXN * BCAP];

// ---- packed fp32x2 helpers (Blackwell FFMA2) ------------------------------
__device__ __forceinline__ unsigned long long pack2(float a, float b) {
    unsigned long long r;
    asm("mov.b64 %0, {%1, %2};" : "=l"(r) : "f"(a), "f"(b));
    return r;
}
__device__ __forceinline__ void fma2(unsigned long long& d,
                                     unsigned long long a, unsigned long long b) {
    asm("fma.rn.f32x2 %0, %1, %2, %0;" : "+l"(d) : "l"(a), "l"(b));
}
__device__ __forceinline__ float2 unpack2(unsigned long long v) {
    float2 r;
    asm("mov.b64 {%0, %1}, %2;" : "=f"(r.x), "=f"(r.y) : "l"(v));
    return r;
}

// ---------------------------------------------------------------------------
// Projection GEMM: C[64 x 128] tile = x[64 x 128] @ W[128 x 128] + bias
// 128 threads, per-thread 8x8 microtile via FFMA2 (4 packed cols).
// ---------------------------------------------------------------------------
__device__ __forceinline__ void gemm_chunk(
    const float (*Ast)[66], float (*Bs)[128],
    const float* __restrict__ W, const float* __restrict__ bias,
    float* __restrict__ O, int tx, int ty, int row0, int n, int tid)
{
    unsigned long long acc[8][4];
#pragma unroll
    for (int i = 0; i < 8; ++i)
#pragma unroll
        for (int j = 0; j < 4; ++j) acc[i][j] = 0ull;

    for (int s = 0; s < 8; ++s) {
        __syncthreads();
        // load 16 K-rows of W into Bs (coalesced float4)
#pragma unroll
        for (int i = tid; i < 16 * 32; i += 128) {
            int r = i >> 5, c4 = i & 31;
            *(float4*)&Bs[r][c4 * 4] =
                *(const float4*)&W[(s * 16 + r) * 128 + c4 * 4];
        }
        __syncthreads();
#pragma unroll
        for (int kk = 0; kk < 16; ++kk) {
            float a[8];
#pragma unroll
            for (int i2 = 0; i2 < 4; ++i2) {
                float2 t = *(const float2*)&Ast[s * 16 + kk][ty * 8 + i2 * 2];
                a[2 * i2] = t.x; a[2 * i2 + 1] = t.y;
            }
            ulonglong2 b0 = *(const ulonglong2*)&Bs[kk][tx * 4];
            ulonglong2 b1 = *(const ulonglong2*)&Bs[kk][64 + tx * 4];
#pragma unroll
            for (int i = 0; i < 8; ++i) {
                unsigned long long a2 = pack2(a[i], a[i]);
                fma2(acc[i][0], a2, b0.x);
                fma2(acc[i][1], a2, b0.y);
                fma2(acc[i][2], a2, b1.x);
                fma2(acc[i][3], a2, b1.y);
            }
        }
    }
    // epilogue: bias + store
    float4 bA = *(const float4*)&bias[tx * 4];
    float4 bB = *(const float4*)&bias[64 + tx * 4];
#pragma unroll
    for (int i = 0; i < 8; ++i) {
        int node = row0 + ty * 8 + i;
        if (node < n) {
            float2 p0 = unpack2(acc[i][0]);
            float2 p1 = unpack2(acc[i][1]);
            float2 p2 = unpack2(acc[i][2]);
            float2 p3 = unpack2(acc[i][3]);
            float4 rA = make_float4(p0.x + bA.x, p0.y + bA.y, p1.x + bA.z, p1.y + bA.w);
            float4 rB = make_float4(p2.x + bB.x, p2.y + bB.y, p3.x + bB.z, p3.y + bB.w);
            *(float4*)&O[node * 128 + tx * 4] = rA;
            *(float4*)&O[node * 128 + 64 + tx * 4] = rB;
        }
    }
}

__global__ void __launch_bounds__(128)
proj_kernel(const float* __restrict__ x,
            const float* __restrict__ Wq, const float* __restrict__ bq,
            const float* __restrict__ Wk, const float* __restrict__ bk,
            const float* __restrict__ Wv, const float* __restrict__ bv,
            const float* __restrict__ Ws, const float* __restrict__ bs,
            int n)
{
    __shared__ __align__(16) float Ast[128][66];   // x tile, transposed, padded
    __shared__ __align__(16) float Bs[16][128];    // W slice

    int tid = threadIdx.x;
    int tx = tid & 15, ty = tid >> 4;
    int row0 = blockIdx.x * 64;

    // load x tile transposed (coalesced global reads; 2-way smem store conflict)
    for (int i = tid; i < 64 * 128; i += 128) {
        int c = i & 127, r = i >> 7;
        int node = row0 + r;
        Ast[c][r] = (node < n) ? x[node * 128 + c] : 0.f;
    }

    const float* Wlist[4] = {Wq, Wk, Wv, Ws};
    const float* blist[4] = {bq, bk, bv, bs};
    float* Olist[4] = {d_qbuf, d_kbuf, d_vbuf, d_sbuf};

#pragma unroll
    for (int w = 0; w < 4; ++w) {
        gemm_chunk(Ast, Bs, Wlist[w], blist[w], Olist[w], tx, ty, row0, n, tid);
    }
}

// ---------------------------------------------------------------------------
// g[n, h*16+d] = sum_c q[n, h*32+c] * We[d, h*32+c]
// ---------------------------------------------------------------------------
__global__ void __launch_bounds__(256)
gfold_kernel(const float* __restrict__ We, int n)
{
    __shared__ float sWe[16][128];
    __shared__ float sq[32][128];
    int tid = threadIdx.x;
    for (int i = tid; i < 2048; i += 256) sWe[i >> 7][i & 127] = We[i];
    int n0 = blockIdx.x * 32;
    for (int i = tid; i < 32 * 128; i += 256) {
        int r = i >> 7, c = i & 127;
        int node = n0 + r;
        sq[r][c] = (node < n) ? d_qbuf[node * 128 + c] : 0.f;
    }
    __syncthreads();
    for (int i = tid; i < 32 * 64; i += 256) {
        int r = i >> 6;
        int o = i & 63;
        int h = o >> 4, d = o & 15;
        float s = 0.f;
#pragma unroll
        for (int c = 0; c < 32; ++c)
            s += sq[r][h * 32 + c] * sWe[d][h * 32 + c];
        int node = n0 + r;
        if (node < n) d_gbuf[node * 64 + o] = s;
    }
}

// ---------------------------------------------------------------------------
// Edge bucketing by destination node
// ---------------------------------------------------------------------------
__global__ void zero_counts(int n) {
    int i = blockIdx.x * blockDim.x + threadIdx.x;
    if (i < n) d_count[i] = 0;
}

__global__ void fill_buckets(const int* __restrict__ row, int e) {
    int i = blockIdx.x * blockDim.x + threadIdx.x;
    if (i >= e) return;
    int dst = row[i];
    int pos = atomicAdd(&d_count[dst], 1);
    if (pos < BCAP) d_bucket[dst * BCAP + pos] = i;
}

// ---------------------------------------------------------------------------
// Warp-per-node softmax aggregation + gated skip (fused final output)
// lane -> 4 channels (float4); head h = lane>>3 owns lanes [8h, 8h+8)
// ---------------------------------------------------------------------------
__global__ void __launch_bounds__(256)
agg_kernel(const int* __restrict__ col,
           const float* __restrict__ edge_attr,
           const float* __restrict__ Wbeta,
           float* __restrict__ out, int n)
{
    int warp = (blockIdx.x * blockDim.x + threadIdx.x) >> 5;
    int lane = threadIdx.x & 31;
    if (warp >= n) return;
    int node = warp;
    int l8 = lane & 7;
    int h = lane >> 3;

    float4 q4 = *(const float4*)&d_qbuf[node * 128 + lane * 4];
    float2 g2 = *(const float2*)&d_gbuf[node * 64 + h * 16 + l8 * 2];

    int deg = d_count[node];
    if (deg > BCAP) deg = BCAP;

    float4 acc = make_float4(0.f, 0.f, 0.f, 0.f);
    float den = 0.f;

    for (int j = 0; j < deg; ++j) {
        int e = d_bucket[node * BCAP + j];
        int src = col[e];
        float4 k4 = *(const float4*)&d_kbuf[src * 128 + lane * 4];
        float4 v4 = *(const float4*)&d_vbuf[src * 128 + lane * 4];
        float2 ea2 = *(const float2*)&edge_attr[e * 16 + l8 * 2];

        float dot = q4.x * k4.x + q4.y * k4.y + q4.z * k4.z + q4.w * k4.w
                  + g2.x * ea2.x + g2.y * ea2.y;
        dot += __shfl_xor_sync(0xffffffffu, dot, 1);
        dot += __shfl_xor_sync(0xffffffffu, dot, 2);
        dot += __shfl_xor_sync(0xffffffffu, dot, 4);
        // 1/sqrt(32)
        float ex = __expf(dot * 0.17677669529663687f);
        den += ex;
        acc.x += ex * v4.x; acc.y += ex * v4.y;
        acc.z += ex * v4.z; acc.w += ex * v4.w;
    }

    float inv = 1.f / (den + 1e-16f);
    float4 o4 = make_float4(acc.x * inv, acc.y * inv, acc.z * inv, acc.w * inv);
    float4 xs4 = *(const float4*)&d_sbuf[node * 128 + lane * 4];

    // beta = sigmoid(out.(Wb0+Wb2) + xs.(Wb1-Wb2))
    float4 wb0 = *(const float4*)&Wbeta[lane * 4];
    float4 wb1 = *(const float4*)&Wbeta[128 + lane * 4];
    float4 wb2 = *(const float4*)&Wbeta[256 + lane * 4];
    float s = o4.x * (wb0.x + wb2.x) + o4.y * (wb0.y + wb2.y)
            + o4.z * (wb0.z + wb2.z) + o4.w * (wb0.w + wb2.w)
            + xs4.x * (wb1.x - wb2.x) + xs4.y * (wb1.y - wb2.y)
            + xs4.z * (wb1.z - wb2.z) + xs4.w * (wb1.w - wb2.w);
    s += __shfl_xor_sync(0xffffffffu, s, 1);
    s += __shfl_xor_sync(0xffffffffu, s, 2);
    s += __shfl_xor_sync(0xffffffffu, s, 4);
    s += __shfl_xor_sync(0xffffffffu, s, 8);
    s += __shfl_xor_sync(0xffffffffu, s, 16);
    float beta = 1.f / (1.f + __expf(-s));

    float4 r;
    r.x = beta * xs4.x + (1.f - beta) * o4.x;
    r.y = beta * xs4.y + (1.f - beta) * o4.y;
    r.z = beta * xs4.z + (1.f - beta) * o4.z;
    r.w = beta * xs4.w + (1.f - beta) * o4.w;
    *(float4*)&out[node * 128 + lane * 4] = r;
}

// ---------------------------------------------------------------------------
extern "C" void kernel_launch(void* const* d_in, const int* in_sizes, int n_in,
                              void* d_out, int out_size)
{
    const float* x         = (const float*)d_in[0];
    const float* edge_attr = (const float*)d_in[1];
    const int*   edge_idx  = (const int*)  d_in[2];
    const float* Wq = (const float*)d_in[3];
    const float* bq = (const float*)d_in[4];
    const float* Wk = (const float*)d_in[5];
    const float* bk = (const float*)d_in[6];
    const float* Wv = (const float*)d_in[7];
    const float* bv = (const float*)d_in[8];
    const float* We = (const float*)d_in[9];
    const float* Ws = (const float*)d_in[10];
    const float* bs = (const float*)d_in[11];
    const float* Wbeta = (const float*)d_in[12];
    float* out = (float*)d_out;

    int n = in_sizes[0] / 128;
    int e = in_sizes[1] / 16;
    const int* row = edge_idx;       // destination nodes
    const int* colv = edge_idx + e;  // source nodes

    proj_kernel<<<(n + 63) / 64, 128>>>(x, Wq, bq, Wk, bk, Wv, bv, Ws, bs, n);
    gfold_kernel<<<(n + 31) / 32, 256>>>(We, n);
    zero_counts<<<(n + 255) / 256, 256>>>(n);
    fill_buckets<<<(e + 255) / 256, 256>>>(row, e);
    agg_kernel<<<((long long)n * 32 + 255) / 256, 256>>>(colv, edge_attr, Wbeta, out, n);
}

// round 3
// speedup vs baseline: 1.1199x; 1.1199x over previous
#include <cuda_runtime.h>
#include <cuda_bf16.h>
#include <cuda_fp16.h>
#include <cstdint>

// ---------------------------------------------------------------------------
// TransformerConv: N=100000 nodes, E=1600000 edges, IN=128, H=4, C=32, ED=16
//
// sm_103 base target (NO tcgen05 — harness PTX is .target sm_103):
//   1) prepack_kernel: W{q,k,v,skip} -> bf16 hi/lo, transposed to [512 x 128]
//   2) proj_mma      : q,s (fp32) + packed fp16 k,v via mma.sync bf16 hi/lo
//   3) gfold_kernel  : g[n,h,d] = sum_c q[n,h,c] * We[d, h*32+c]
//   4) zero_counts / fill_buckets: bucket edges by destination node
//   5) agg_kernel    : warp-per-dst-node, batched-shfl + prefetch-4 gathers,
//                      softmax aggregation + gated skip fused
// ---------------------------------------------------------------------------

#define MAXN 100096
#define BCAP 96   // per-node bucket capacity (Poisson(16) max ~36; 96 is safe)

__device__ float d_qbuf[MAXN * 128];
__device__ float d_sbuf[MAXN * 128];
__device__ float d_gbuf[MAXN * 64];
__device__ uint4 d_kv[MAXN * 32];           // per node: 32 lanes x 16B {k4 half, v4 half}
__device__ int   d_count[MAXN];
__device__ int   d_bucket[MAXN * BCAP];
__device__ __nv_bfloat16 d_Bhi[512 * 128];  // W^T hi, n-major rows, k cols
__device__ __nv_bfloat16 d_Blo[512 * 128];  // W^T lo

// ============================ helpers ======================================
__device__ __forceinline__ uint32_t smem_u32(const void* p) {
    uint32_t a;
    asm("{ .reg .u64 t; cvta.to.shared.u64 t, %1; cvt.u32.u64 %0, t; }"
        : "=r"(a) : "l"(p));
    return a;
}
__device__ __forceinline__ void ldm_x4(uint32_t& r0, uint32_t& r1,
                                       uint32_t& r2, uint32_t& r3, uint32_t addr) {
    asm volatile("ldmatrix.sync.aligned.m8n8.x4.shared.b16 {%0,%1,%2,%3}, [%4];"
                 : "=r"(r0), "=r"(r1), "=r"(r2), "=r"(r3) : "r"(addr));
}
__device__ __forceinline__ void ldm_x2(uint32_t& r0, uint32_t& r1, uint32_t addr) {
    asm volatile("ldmatrix.sync.aligned.m8n8.x2.shared.b16 {%0,%1}, [%2];"
                 : "=r"(r0), "=r"(r1) : "r"(addr));
}
__device__ __forceinline__ void mma_bf16(float* c, const uint32_t* a,
                                         uint32_t b0, uint32_t b1) {
    asm volatile(
        "mma.sync.aligned.m16n8k16.row.col.f32.bf16.bf16.f32 "
        "{%0,%1,%2,%3}, {%4,%5,%6,%7}, {%8,%9}, {%0,%1,%2,%3};"
        : "+f"(c[0]), "+f"(c[1]), "+f"(c[2]), "+f"(c[3])
        : "r"(a[0]), "r"(a[1]), "r"(a[2]), "r"(a[3]), "r"(b0), "r"(b1));
}
__device__ __forceinline__ uint32_t pkbf(__nv_bfloat16 a, __nv_bfloat16 b) {
    return (uint32_t)__bfloat16_as_ushort(a)
         | ((uint32_t)__bfloat16_as_ushort(b) << 16);
}

// ---------------------------------------------------------------------------
// prepack: W[k][col] (4 matrices) -> Bhi/Blo[n=4*128 rows][k=128] bf16 hi/lo
// ---------------------------------------------------------------------------
__global__ void __launch_bounds__(256)
prepack_kernel(const float* __restrict__ Wq, const float* __restrict__ Wk,
               const float* __restrict__ Wv, const float* __restrict__ Ws)
{
    int i = blockIdx.x * 256 + threadIdx.x;   // 65536 elements
    if (i >= 512 * 128) return;
    int k = i >> 9, nn = i & 511;
    int w = nn >> 7, c = nn & 127;
    const float* W = (w == 0) ? Wq : (w == 1) ? Wk : (w == 2) ? Wv : Ws;
    float v = W[k * 128 + c];
    __nv_bfloat16 h = __float2bfloat16(v);
    float lo = v - __bfloat162float(h);
    d_Bhi[nn * 128 + k] = h;
    d_Blo[nn * 128 + k] = __float2bfloat16(lo);
}

// ---------------------------------------------------------------------------
// Projection via mma.sync: per CTA M=128 tile, 4 N-chunks (q,k,v,skip)
// smem rows padded to 136 halves (272B) -> conflict-free ldmatrix
// ---------------------------------------------------------------------------
#define ASTR 136
#define PROJ_SMEM (4 * 128 * ASTR * 2)

__global__ void __launch_bounds__(256, 1)
proj_mma(const float* __restrict__ x,
         const float* __restrict__ bq, const float* __restrict__ bk,
         const float* __restrict__ bv, const float* __restrict__ bs,
         int n)
{
    extern __shared__ __align__(16) char smem[];
    ushort* sA_hi = (ushort*)smem;                 // [128][ASTR]
    ushort* sA_lo = sA_hi + 128 * ASTR;
    ushort* sB_hi = sA_lo + 128 * ASTR;
    ushort* sB_lo = sB_hi + 128 * ASTR;

    int tid = threadIdx.x, lane = tid & 31, wid = tid >> 5;
    int row0 = blockIdx.x * 128;

    // Stage x tile -> bf16 hi/lo
    for (int i = tid; i < 128 * 32; i += 256) {
        int r = i >> 5, c4 = i & 31;
        int node = row0 + r;
        float4 xv = (node < n) ? *(const float4*)&x[node * 128 + c4 * 4]
                               : make_float4(0.f, 0.f, 0.f, 0.f);
        __nv_bfloat16 h0 = __float2bfloat16(xv.x);
        __nv_bfloat16 h1 = __float2bfloat16(xv.y);
        __nv_bfloat16 h2 = __float2bfloat16(xv.z);
        __nv_bfloat16 h3 = __float2bfloat16(xv.w);
        __nv_bfloat16 l0 = __float2bfloat16(xv.x - __bfloat162float(h0));
        __nv_bfloat16 l1 = __float2bfloat16(xv.y - __bfloat162float(h1));
        __nv_bfloat16 l2 = __float2bfloat16(xv.z - __bfloat162float(h2));
        __nv_bfloat16 l3 = __float2bfloat16(xv.w - __bfloat162float(h3));
        *(uint2*)&sA_hi[r * ASTR + c4 * 4] = make_uint2(pkbf(h0, h1), pkbf(h2, h3));
        *(uint2*)&sA_lo[r * ASTR + c4 * 4] = make_uint2(pkbf(l0, l1), pkbf(l2, l3));
    }

    uint32_t uAhi = smem_u32(sA_hi), uAlo = smem_u32(sA_lo);
    uint32_t uBhi = smem_u32(sB_hi), uBlo = smem_u32(sB_lo);

    const float* biasl[4] = {bq, bk, bv, bs};
    ushort* kvs = (ushort*)d_kv;

    for (int nc = 0; nc < 4; ++nc) {
        __syncthreads();
        // Stage W chunk [128 n][128 k] hi/lo
        for (int i = tid; i < 128 * 16; i += 256) {
            int r = i >> 4, c8 = i & 15;
            int gidx = (nc * 128 + r) * 128 + c8 * 8;
            *(uint4*)&sB_hi[r * ASTR + c8 * 8] = *(const uint4*)&d_Bhi[gidx];
            *(uint4*)&sB_lo[r * ASTR + c8 * 8] = *(const uint4*)&d_Blo[gidx];
        }
        __syncthreads();

        float acc[16][4];
#pragma unroll
        for (int f = 0; f < 16; ++f)
#pragma unroll
            for (int j = 0; j < 4; ++j) acc[f][j] = 0.f;

        uint32_t a_row = (uint32_t)(wid * 16 + (lane & 15));
        uint32_t a_koff = (uint32_t)((lane >> 4) * 8);
        uint32_t b_row = (uint32_t)(lane & 7);
        uint32_t b_koff = (uint32_t)(((lane >> 3) & 1) * 8);

#pragma unroll
        for (int ks = 0; ks < 8; ++ks) {
            uint32_t aoff = (a_row * ASTR + ks * 16 + a_koff) * 2;
            uint32_t ah[4], al[4];
            ldm_x4(ah[0], ah[1], ah[2], ah[3], uAhi + aoff);
            ldm_x4(al[0], al[1], al[2], al[3], uAlo + aoff);
#pragma unroll
            for (int nf = 0; nf < 16; ++nf) {
                uint32_t boff = ((nf * 8 + b_row) * ASTR + ks * 16 + b_koff) * 2;
                uint32_t bh0, bh1, bl0, bl1;
                ldm_x2(bh0, bh1, uBhi + boff);
                ldm_x2(bl0, bl1, uBlo + boff);
                mma_bf16(acc[nf], ah, bh0, bh1);
                mma_bf16(acc[nf], ah, bl0, bl1);
                mma_bf16(acc[nf], al, bh0, bh1);
            }
        }

        // Epilogue
        const float* bias = biasl[nc];
        int r_base = row0 + wid * 16 + (lane >> 2);
#pragma unroll
        for (int nf = 0; nf < 16; ++nf) {
            int cn = nf * 8 + (lane & 3) * 2;
            float b0 = __ldg(&bias[cn]), b1 = __ldg(&bias[cn + 1]);
#pragma unroll
            for (int half = 0; half < 2; ++half) {
                int node = r_base + half * 8;
                if (node >= n) continue;
                float v0 = acc[nf][half * 2 + 0] + b0;
                float v1 = acc[nf][half * 2 + 1] + b1;
                if (nc == 0) {
                    *(float2*)&d_qbuf[node * 128 + cn] = make_float2(v0, v1);
                } else if (nc == 3) {
                    *(float2*)&d_sbuf[node * 128 + cn] = make_float2(v0, v1);
                } else {
                    __half2 hh = __floats2half2_rn(v0, v1);
                    uint32_t idx = (uint32_t)node * 256 + ((cn >> 2) << 3)
                                 + (cn & 3) + (nc == 2 ? 4 : 0);
                    *(uint32_t*)&kvs[idx] = *(uint32_t*)&hh;
                }
            }
        }
    }
}

// ---------------------------------------------------------------------------
// g[n, h*16+d] = sum_c q[n, h*32+c] * We[d, h*32+c]
// ---------------------------------------------------------------------------
__global__ void __launch_bounds__(256)
gfold_kernel(const float* __restrict__ We, int n)
{
    __shared__ float sWe[16][128];
    __shared__ float sq[32][128];
    int tid = threadIdx.x;
    for (int i = tid; i < 2048; i += 256) sWe[i >> 7][i & 127] = We[i];
    int n0 = blockIdx.x * 32;
    for (int i = tid; i < 32 * 128; i += 256) {
        int r = i >> 7, c = i & 127;
        int node = n0 + r;
        sq[r][c] = (node < n) ? d_qbuf[node * 128 + c] : 0.f;
    }
    __syncthreads();
    for (int i = tid; i < 32 * 64; i += 256) {
        int r = i >> 6;
        int o = i & 63;
        int h = o >> 4, d = o & 15;
        float s = 0.f;
#pragma unroll
        for (int c = 0; c < 32; ++c)
            s += sq[r][h * 32 + c] * sWe[d][h * 32 + c];
        int node = n0 + r;
        if (node < n) d_gbuf[node * 64 + o] = s;
    }
}

// ---------------------------------------------------------------------------
// Edge bucketing by destination node
// ---------------------------------------------------------------------------
__global__ void zero_counts(int n) {
    int i = blockIdx.x * blockDim.x + threadIdx.x;
    if (i < n) d_count[i] = 0;
}

__global__ void fill_buckets(const int* __restrict__ row, int e) {
    int i = blockIdx.x * blockDim.x + threadIdx.x;
    if (i >= e) return;
    int dst = row[i];
    int pos = atomicAdd(&d_count[dst], 1);
    if (pos < BCAP) d_bucket[dst * BCAP + pos] = i;
}

// ---------------------------------------------------------------------------
// Warp-per-node softmax aggregation + gated skip.
// Batched edge-id/src preload (coalesced) + shfl broadcast + prefetch-4.
// ---------------------------------------------------------------------------
__global__ void __launch_bounds__(256)
agg_kernel(const int* __restrict__ col,
           const float* __restrict__ edge_attr,
           const float* __restrict__ Wbeta,
           float* __restrict__ out, int n)
{
    int warp = (blockIdx.x * blockDim.x + threadIdx.x) >> 5;
    int lane = threadIdx.x & 31;
    if (warp >= n) return;
    int node = warp;
    int l8 = lane & 7;
    int h = lane >> 3;

    float4 q4 = *(const float4*)&d_qbuf[node * 128 + lane * 4];
    float2 g2 = *(const float2*)&d_gbuf[node * 64 + h * 16 + l8 * 2];

    int deg = d_count[node];
    if (deg > BCAP) deg = BCAP;

    float4 acc = make_float4(0.f, 0.f, 0.f, 0.f);
    float den = 0.f;

    for (int j0 = 0; j0 < deg; j0 += 32) {
        int jb = min(32, deg - j0);
        int e_l = 0, s_l = 0;
        if (lane < jb) {
            e_l = d_bucket[node * BCAP + j0 + lane];
            s_l = col[e_l];
        }
        int j = 0;
        for (; j + 4 <= jb; j += 4) {
            uint4 kvv[4];
            float2 ea[4];
#pragma unroll
            for (int t = 0; t < 4; ++t) {
                int e   = __shfl_sync(0xffffffffu, e_l, j + t);
                int src = __shfl_sync(0xffffffffu, s_l, j + t);
                kvv[t] = __ldg(&d_kv[src * 32 + lane]);
                ea[t]  = *(const float2*)&edge_attr[e * 16 + l8 * 2];
            }
#pragma unroll
            for (int t = 0; t < 4; ++t) {
                float2 k01 = __half22float2(*(__half2*)&kvv[t].x);
                float2 k23 = __half22float2(*(__half2*)&kvv[t].y);
                float2 v01 = __half22float2(*(__half2*)&kvv[t].z);
                float2 v23 = __half22float2(*(__half2*)&kvv[t].w);
                float dot = q4.x * k01.x + q4.y * k01.y + q4.z * k23.x + q4.w * k23.y
                          + g2.x * ea[t].x + g2.y * ea[t].y;
                dot += __shfl_xor_sync(0xffffffffu, dot, 1);
                dot += __shfl_xor_sync(0xffffffffu, dot, 2);
                dot += __shfl_xor_sync(0xffffffffu, dot, 4);
                float ex = __expf(dot * 0.17677669529663687f);  // 1/sqrt(32)
                den += ex;
                acc.x += ex * v01.x; acc.y += ex * v01.y;
                acc.z += ex * v23.x; acc.w += ex * v23.y;
            }
        }
        for (; j < jb; ++j) {
            int e   = __shfl_sync(0xffffffffu, e_l, j);
            int src = __shfl_sync(0xffffffffu, s_l, j);
            uint4 kvv = __ldg(&d_kv[src * 32 + lane]);
            float2 ea = *(const float2*)&edge_attr[e * 16 + l8 * 2];
            float2 k01 = __half22float2(*(__half2*)&kvv.x);
            float2 k23 = __half22float2(*(__half2*)&kvv.y);
            float2 v01 = __half22float2(*(__half2*)&kvv.z);
            float2 v23 = __half22float2(*(__half2*)&kvv.w);
            float dot = q4.x * k01.x + q4.y * k01.y + q4.z * k23.x + q4.w * k23.y
                      + g2.x * ea.x + g2.y * ea.y;
            dot += __shfl_xor_sync(0xffffffffu, dot, 1);
            dot += __shfl_xor_sync(0xffffffffu, dot, 2);
            dot += __shfl_xor_sync(0xffffffffu, dot, 4);
            float ex = __expf(dot * 0.17677669529663687f);
            den += ex;
            acc.x += ex * v01.x; acc.y += ex * v01.y;
            acc.z += ex * v23.x; acc.w += ex * v23.y;
        }
    }

    float inv = 1.f / (den + 1e-16f);
    float4 o4 = make_float4(acc.x * inv, acc.y * inv, acc.z * inv, acc.w * inv);
    float4 xs4 = *(const float4*)&d_sbuf[node * 128 + lane * 4];

    // beta = sigmoid(out.(Wb0+Wb2) + xs.(Wb1-Wb2))
    float4 wb0 = *(const float4*)&Wbeta[lane * 4];
    float4 wb1 = *(const float4*)&Wbeta[128 + lane * 4];
    float4 wb2 = *(const float4*)&Wbeta[256 + lane * 4];
    float s = o4.x * (wb0.x + wb2.x) + o4.y * (wb0.y + wb2.y)
            + o4.z * (wb0.z + wb2.z) + o4.w * (wb0.w + wb2.w)
            + xs4.x * (wb1.x - wb2.x) + xs4.y * (wb1.y - wb2.y)
            + xs4.z * (wb1.z - wb2.z) + xs4.w * (wb1.w - wb2.w);
    s += __shfl_xor_sync(0xffffffffu, s, 1);
    s += __shfl_xor_sync(0xffffffffu, s, 2);
    s += __shfl_xor_sync(0xffffffffu, s, 4);
    s += __shfl_xor_sync(0xffffffffu, s, 8);
    s += __shfl_xor_sync(0xffffffffu, s, 16);
    float beta = 1.f / (1.f + __expf(-s));

    float4 r;
    r.x = beta * xs4.x + (1.f - beta) * o4.x;
    r.y = beta * xs4.y + (1.f - beta) * o4.y;
    r.z = beta * xs4.z + (1.f - beta) * o4.z;
    r.w = beta * xs4.w + (1.f - beta) * o4.w;
    *(float4*)&out[node * 128 + lane * 4] = r;
}

// ---------------------------------------------------------------------------
extern "C" void kernel_launch(void* const* d_in, const int* in_sizes, int n_in,
                              void* d_out, int out_size)
{
    const float* x         = (const float*)d_in[0];
    const float* edge_attr = (const float*)d_in[1];
    const int*   edge_idx  = (const int*)  d_in[2];
    const float* Wq = (const float*)d_in[3];
    const float* bq = (const float*)d_in[4];
    const float* Wk = (const float*)d_in[5];
    const float* bk = (const float*)d_in[6];
    const float* Wv = (const float*)d_in[7];
    const float* bv = (const float*)d_in[8];
    const float* We = (const float*)d_in[9];
    const float* Ws = (const float*)d_in[10];
    const float* bs = (const float*)d_in[11];
    const float* Wbeta = (const float*)d_in[12];
    float* out = (float*)d_out;

    int n = in_sizes[0] / 128;
    int e = in_sizes[1] / 16;
    const int* row  = edge_idx;      // destination nodes
    const int* colv = edge_idx + e;  // source nodes

    cudaFuncSetAttribute(proj_mma, cudaFuncAttributeMaxDynamicSharedMemorySize,
                         PROJ_SMEM);

    prepack_kernel<<<256, 256>>>(Wq, Wk, Wv, Ws);
    proj_mma<<<(n + 127) / 128, 256, PROJ_SMEM>>>(x, bq, bk, bv, bs, n);
    gfold_kernel<<<(n + 31) / 32, 256>>>(We, n);
    zero_counts<<<(n + 255) / 256, 256>>>(n);
    fill_buckets<<<(e + 255) / 256, 256>>>(row, e);
    agg_kernel<<<((long long)n * 32 + 255) / 256, 256>>>(colv, edge_attr, Wbeta, out, n);
}

// round 4
// speedup vs baseline: 1.6040x; 1.4323x over previous
#include <cuda_runtime.h>
#include <cuda_bf16.h>
#include <cuda_fp16.h>
#include <cstdint>

// ---------------------------------------------------------------------------
// TransformerConv: N=100000 nodes, E=1600000 edges, IN=128, H=4, C=32, ED=16
//
// sm_103 base target (NO tcgen05 — harness PTX is .target sm_103):
//   1) prepack_kernel: W{q,k,v,skip} -> bf16 hi/lo [512x128]; Wg = fold of
//      (Wq, We) -> rows 512..575; zero d_count   (single fused launch)
//   2) fill_buckets  : bucket {edge,src} pairs by destination node
//   3) proj_mma      : q,g (fp32) + packed fp16 k,v + skip via mma.sync
//                      bf16 hi/lo split, 5 N-chunks (q,k,v,skip,g)
//   4) agg_kernel    : warp-per-dst-node, batched-shfl + prefetch-4 gathers,
//                      softmax aggregation + gated skip fused
// ---------------------------------------------------------------------------

#define MAXN 100096
#define BCAP 96   // per-node bucket capacity (Poisson(16) max ~36; 96 is safe)

__device__ float d_qbuf[MAXN * 128];
__device__ float d_sbuf[MAXN * 128];
__device__ float d_gbuf[MAXN * 64];
__device__ uint4 d_kv[MAXN * 32];           // per node: 32 lanes x 16B {k4 half, v4 half}
__device__ int   d_count[MAXN];
__device__ int2  d_bucket[MAXN * BCAP];     // {edge id, src node}
__device__ __nv_bfloat16 d_Bhi[576 * 128];  // W^T hi, n-major rows, k cols (+Wg)
__device__ __nv_bfloat16 d_Blo[576 * 128];  // W^T lo
__device__ float d_bg[64];                  // bias for folded g projection

// ============================ helpers ======================================
__device__ __forceinline__ uint32_t smem_u32(const void* p) {
    uint32_t a;
    asm("{ .reg .u64 t; cvta.to.shared.u64 t, %1; cvt.u32.u64 %0, t; }"
        : "=r"(a) : "l"(p));
    return a;
}
__device__ __forceinline__ void ldm_x4(uint32_t& r0, uint32_t& r1,
                                       uint32_t& r2, uint32_t& r3, uint32_t addr) {
    asm volatile("ldmatrix.sync.aligned.m8n8.x4.shared.b16 {%0,%1,%2,%3}, [%4];"
                 : "=r"(r0), "=r"(r1), "=r"(r2), "=r"(r3) : "r"(addr));
}
__device__ __forceinline__ void ldm_x2(uint32_t& r0, uint32_t& r1, uint32_t addr) {
    asm volatile("ldmatrix.sync.aligned.m8n8.x2.shared.b16 {%0,%1}, [%2];"
                 : "=r"(r0), "=r"(r1) : "r"(addr));
}
__device__ __forceinline__ void mma_bf16(float* c, const uint32_t* a,
                                         uint32_t b0, uint32_t b1) {
    asm volatile(
        "mma.sync.aligned.m16n8k16.row.col.f32.bf16.bf16.f32 "
        "{%0,%1,%2,%3}, {%4,%5,%6,%7}, {%8,%9}, {%0,%1,%2,%3};"
        : "+f"(c[0]), "+f"(c[1]), "+f"(c[2]), "+f"(c[3])
        : "r"(a[0]), "r"(a[1]), "r"(a[2]), "r"(a[3]), "r"(b0), "r"(b1));
}
__device__ __forceinline__ uint32_t pkbf(__nv_bfloat16 a, __nv_bfloat16 b) {
    return (uint32_t)__bfloat16_as_ushort(a)
         | ((uint32_t)__bfloat16_as_ushort(b) << 16);
}

// ---------------------------------------------------------------------------
// prepack (fused): blocks [0,256): W pack; [256,288): Wg fold; [288,679): zero
// ---------------------------------------------------------------------------
__global__ void __launch_bounds__(256)
prepack_kernel(const float* __restrict__ Wq, const float* __restrict__ Wk,
               const float* __restrict__ Wv, const float* __restrict__ Ws,
               const float* __restrict__ We, const float* __restrict__ bq)
{
    int b = blockIdx.x, tid = threadIdx.x;
    if (b < 256) {
        int i = b * 256 + tid;               // 65536 elements
        int k = i >> 9, nn = i & 511;
        int w = nn >> 7, c = nn & 127;
        const float* W = (w == 0) ? Wq : (w == 1) ? Wk : (w == 2) ? Wv : Ws;
        float v = W[k * 128 + c];
        __nv_bfloat16 h = __float2bfloat16(v);
        d_Bhi[nn * 128 + k] = h;
        d_Blo[nn * 128 + k] = __float2bfloat16(v - __bfloat162float(h));
    } else if (b < 288) {
        int t = (b - 256) * 256 + tid;       // 8192: (i, o)
        int i = t >> 6, o = t & 63;
        int h = o >> 4, d = o & 15;
        float s = 0.f;
#pragma unroll
        for (int c = 0; c < 32; ++c)
            s += Wq[i * 128 + h * 32 + c] * We[d * 128 + h * 32 + c];
        __nv_bfloat16 hh = __float2bfloat16(s);
        d_Bhi[(512 + o) * 128 + i] = hh;
        d_Blo[(512 + o) * 128 + i] = __float2bfloat16(s - __bfloat162float(hh));
        if (i == 0) {
            float sb = 0.f;
#pragma unroll
            for (int c = 0; c < 32; ++c)
                sb += bq[h * 32 + c] * We[d * 128 + h * 32 + c];
            d_bg[o] = sb;
        }
    } else {
        int i = (b - 288) * 256 + tid;
        if (i < MAXN) d_count[i] = 0;
    }
}

// ---------------------------------------------------------------------------
// Edge bucketing: store {edge, src} pairs (kills a dependent load in agg)
// ---------------------------------------------------------------------------
__global__ void __launch_bounds__(256)
fill_buckets(const int* __restrict__ row, const int* __restrict__ colv, int e)
{
    int i = blockIdx.x * blockDim.x + threadIdx.x;
    if (i >= e) return;
    int dst = row[i];
    int src = colv[i];
    int pos = atomicAdd(&d_count[dst], 1);
    if (pos < BCAP) d_bucket[dst * BCAP + pos] = make_int2(i, src);
}

// ---------------------------------------------------------------------------
// Projection via mma.sync: per CTA M=128 tile, 5 N-chunks (q,k,v,skip,g)
// smem rows padded to 136 halves (272B) -> conflict-free ldmatrix
// ---------------------------------------------------------------------------
#define ASTR 136
#define PROJ_SMEM (4 * 128 * ASTR * 2)

__global__ void __launch_bounds__(256, 1)
proj_mma(const float* __restrict__ x,
         const float* __restrict__ bq, const float* __restrict__ bk,
         const float* __restrict__ bv, const float* __restrict__ bs,
         int n)
{
    extern __shared__ __align__(16) char smem[];
    ushort* sA_hi = (ushort*)smem;                 // [128][ASTR]
    ushort* sA_lo = sA_hi + 128 * ASTR;
    ushort* sB_hi = sA_lo + 128 * ASTR;
    ushort* sB_lo = sB_hi + 128 * ASTR;

    int tid = threadIdx.x, lane = tid & 31, wid = tid >> 5;
    int row0 = blockIdx.x * 128;

    // Stage x tile -> bf16 hi/lo
    for (int i = tid; i < 128 * 32; i += 256) {
        int r = i >> 5, c4 = i & 31;
        int node = row0 + r;
        float4 xv = (node < n) ? *(const float4*)&x[node * 128 + c4 * 4]
                               : make_float4(0.f, 0.f, 0.f, 0.f);
        __nv_bfloat16 h0 = __float2bfloat16(xv.x);
        __nv_bfloat16 h1 = __float2bfloat16(xv.y);
        __nv_bfloat16 h2 = __float2bfloat16(xv.z);
        __nv_bfloat16 h3 = __float2bfloat16(xv.w);
        __nv_bfloat16 l0 = __float2bfloat16(xv.x - __bfloat162float(h0));
        __nv_bfloat16 l1 = __float2bfloat16(xv.y - __bfloat162float(h1));
        __nv_bfloat16 l2 = __float2bfloat16(xv.z - __bfloat162float(h2));
        __nv_bfloat16 l3 = __float2bfloat16(xv.w - __bfloat162float(h3));
        *(uint2*)&sA_hi[r * ASTR + c4 * 4] = make_uint2(pkbf(h0, h1), pkbf(h2, h3));
        *(uint2*)&sA_lo[r * ASTR + c4 * 4] = make_uint2(pkbf(l0, l1), pkbf(l2, l3));
    }

    uint32_t uAhi = smem_u32(sA_hi), uAlo = smem_u32(sA_lo);
    uint32_t uBhi = smem_u32(sB_hi), uBlo = smem_u32(sB_lo);

    const float* biasl[4] = {bq, bk, bv, bs};
    ushort* kvs = (ushort*)d_kv;

    for (int nc = 0; nc < 5; ++nc) {
        int NF = (nc == 4) ? 8 : 16;             // g chunk is N=64
        __syncthreads();
        // Stage W chunk [NF*8 n-rows][128 k] hi/lo
        for (int i = tid; i < NF * 8 * 16; i += 256) {
            int r = i >> 4, c8 = i & 15;
            int gidx = (nc * 128 + r) * 128 + c8 * 8;
            *(uint4*)&sB_hi[r * ASTR + c8 * 8] = *(const uint4*)&d_Bhi[gidx];
            *(uint4*)&sB_lo[r * ASTR + c8 * 8] = *(const uint4*)&d_Blo[gidx];
        }
        __syncthreads();

        float acc[16][4];
#pragma unroll
        for (int f = 0; f < 16; ++f)
#pragma unroll
            for (int j = 0; j < 4; ++j) acc[f][j] = 0.f;

        uint32_t a_row = (uint32_t)(wid * 16 + (lane & 15));
        uint32_t a_koff = (uint32_t)((lane >> 4) * 8);
        uint32_t b_row = (uint32_t)(lane & 7);
        uint32_t b_koff = (uint32_t)(((lane >> 3) & 1) * 8);

#pragma unroll
        for (int ks = 0; ks < 8; ++ks) {
            uint32_t aoff = (a_row * ASTR + ks * 16 + a_koff) * 2;
            uint32_t ah[4], al[4];
            ldm_x4(ah[0], ah[1], ah[2], ah[3], uAhi + aoff);
            ldm_x4(al[0], al[1], al[2], al[3], uAlo + aoff);
#pragma unroll
            for (int nf = 0; nf < 16; ++nf) {
                if (nf >= NF) break;
                uint32_t boff = ((nf * 8 + b_row) * ASTR + ks * 16 + b_koff) * 2;
                uint32_t bh0, bh1, bl0, bl1;
                ldm_x2(bh0, bh1, uBhi + boff);
                ldm_x2(bl0, bl1, uBlo + boff);
                mma_bf16(acc[nf], ah, bh0, bh1);
                mma_bf16(acc[nf], ah, bl0, bl1);
                mma_bf16(acc[nf], al, bh0, bh1);
            }
        }

        // Epilogue
        int r_base = row0 + wid * 16 + (lane >> 2);
        if (nc == 4) {
#pragma unroll
            for (int nf = 0; nf < 8; ++nf) {
                int cn = nf * 8 + (lane & 3) * 2;
                float b0 = d_bg[cn], b1 = d_bg[cn + 1];
#pragma unroll
                for (int half = 0; half < 2; ++half) {
                    int node = r_base + half * 8;
                    if (node >= n) continue;
                    *(float2*)&d_gbuf[node * 64 + cn] =
                        make_float2(acc[nf][half * 2] + b0, acc[nf][half * 2 + 1] + b1);
                }
            }
        } else {
            const float* bias = biasl[nc];
#pragma unroll
            for (int nf = 0; nf < 16; ++nf) {
                int cn = nf * 8 + (lane & 3) * 2;
                float b0 = __ldg(&bias[cn]), b1 = __ldg(&bias[cn + 1]);
#pragma unroll
                for (int half = 0; half < 2; ++half) {
                    int node = r_base + half * 8;
                    if (node >= n) continue;
                    float v0 = acc[nf][half * 2 + 0] + b0;
                    float v1 = acc[nf][half * 2 + 1] + b1;
                    if (nc == 0) {
                        *(float2*)&d_qbuf[node * 128 + cn] = make_float2(v0, v1);
                    } else if (nc == 3) {
                        *(float2*)&d_sbuf[node * 128 + cn] = make_float2(v0, v1);
                    } else {
                        __half2 hh = __floats2half2_rn(v0, v1);
                        uint32_t idx = (uint32_t)node * 256 + ((cn >> 2) << 3)
                                     + (cn & 3) + (nc == 2 ? 4 : 0);
                        *(uint32_t*)&kvs[idx] = *(uint32_t*)&hh;
                    }
                }
            }
        }
    }
}

// ---------------------------------------------------------------------------
// Warp-per-node softmax aggregation + gated skip.
// Batched {edge,src} preload (coalesced) + shfl broadcast + prefetch-4.
// ---------------------------------------------------------------------------
__global__ void __launch_bounds__(256)
agg_kernel(const float* __restrict__ edge_attr,
           const float* __restrict__ Wbeta,
           float* __restrict__ out, int n)
{
    int warp = (blockIdx.x * blockDim.x + threadIdx.x) >> 5;
    int lane = threadIdx.x & 31;
    if (warp >= n) return;
    int node = warp;
    int l8 = lane & 7;
    int h = lane >> 3;

    float4 q4 = *(const float4*)&d_qbuf[node * 128 + lane * 4];
    float2 g2 = *(const float2*)&d_gbuf[node * 64 + h * 16 + l8 * 2];

    int deg = d_count[node];
    if (deg > BCAP) deg = BCAP;

    float4 acc = make_float4(0.f, 0.f, 0.f, 0.f);
    float den = 0.f;

    for (int j0 = 0; j0 < deg; j0 += 32) {
        int jb = min(32, deg - j0);
        int e_l = 0, s_l = 0;
        if (lane < jb) {
            int2 es = d_bucket[node * BCAP + j0 + lane];
            e_l = es.x; s_l = es.y;
        }
        int j = 0;
        for (; j + 4 <= jb; j += 4) {
            uint4 kvv[4];
            float2 ea[4];
#pragma unroll
            for (int t = 0; t < 4; ++t) {
                int e   = __shfl_sync(0xffffffffu, e_l, j + t);
                int src = __shfl_sync(0xffffffffu, s_l, j + t);
                kvv[t] = __ldg(&d_kv[src * 32 + lane]);
                ea[t]  = *(const float2*)&edge_attr[e * 16 + l8 * 2];
            }
#pragma unroll
            for (int t = 0; t < 4; ++t) {
                float2 k01 = __half22float2(*(__half2*)&kvv[t].x);
                float2 k23 = __half22float2(*(__half2*)&kvv[t].y);
                float2 v01 = __half22float2(*(__half2*)&kvv[t].z);
                float2 v23 = __half22float2(*(__half2*)&kvv[t].w);
                float dot = q4.x * k01.x + q4.y * k01.y + q4.z * k23.x + q4.w * k23.y
                          + g2.x * ea[t].x + g2.y * ea[t].y;
                dot += __shfl_xor_sync(0xffffffffu, dot, 1);
                dot += __shfl_xor_sync(0xffffffffu, dot, 2);
                dot += __shfl_xor_sync(0xffffffffu, dot, 4);
                float ex = __expf(dot * 0.17677669529663687f);  // 1/sqrt(32)
                den += ex;
                acc.x += ex * v01.x; acc.y += ex * v01.y;
                acc.z += ex * v23.x; acc.w += ex * v23.y;
            }
        }
        for (; j < jb; ++j) {
            int e   = __shfl_sync(0xffffffffu, e_l, j);
            int src = __shfl_sync(0xffffffffu, s_l, j);
            uint4 kvv = __ldg(&d_kv[src * 32 + lane]);
            float2 ea = *(const float2*)&edge_attr[e * 16 + l8 * 2];
            float2 k01 = __half22float2(*(__half2*)&kvv.x);
            float2 k23 = __half22float2(*(__half2*)&kvv.y);
            float2 v01 = __half22float2(*(__half2*)&kvv.z);
            float2 v23 = __half22float2(*(__half2*)&kvv.w);
            float dot = q4.x * k01.x + q4.y * k01.y + q4.z * k23.x + q4.w * k23.y
                      + g2.x * ea.x + g2.y * ea.y;
            dot += __shfl_xor_sync(0xffffffffu, dot, 1);
            dot += __shfl_xor_sync(0xffffffffu, dot, 2);
            dot += __shfl_xor_sync(0xffffffffu, dot, 4);
            float ex = __expf(dot * 0.17677669529663687f);
            den += ex;
            acc.x += ex * v01.x; acc.y += ex * v01.y;
            acc.z += ex * v23.x; acc.w += ex * v23.y;
        }
    }

    float inv = 1.f / (den + 1e-16f);
    float4 o4 = make_float4(acc.x * inv, acc.y * inv, acc.z * inv, acc.w * inv);
    float4 xs4 = *(const float4*)&d_sbuf[node * 128 + lane * 4];

    // beta = sigmoid(out.(Wb0+Wb2) + xs.(Wb1-Wb2))
    float4 wb0 = *(const float4*)&Wbeta[lane * 4];
    float4 wb1 = *(const float4*)&Wbeta[128 + lane * 4];
    float4 wb2 = *(const float4*)&Wbeta[256 + lane * 4];
    float s = o4.x * (wb0.x + wb2.x) + o4.y * (wb0.y + wb2.y)
            + o4.z * (wb0.z + wb2.z) + o4.w * (wb0.w + wb2.w)
            + xs4.x * (wb1.x - wb2.x) + xs4.y * (wb1.y - wb2.y)
            + xs4.z * (wb1.z - wb2.z) + xs4.w * (wb1.w - wb2.w);
    s += __shfl_xor_sync(0xffffffffu, s, 1);
    s += __shfl_xor_sync(0xffffffffu, s, 2);
    s += __shfl_xor_sync(0xffffffffu, s, 4);
    s += __shfl_xor_sync(0xffffffffu, s, 8);
    s += __shfl_xor_sync(0xffffffffu, s, 16);
    float beta = 1.f / (1.f + __expf(-s));

    float4 r;
    r.x = beta * xs4.x + (1.f - beta) * o4.x;
    r.y = beta * xs4.y + (1.f - beta) * o4.y;
    r.z = beta * xs4.z + (1.f - beta) * o4.z;
    r.w = beta * xs4.w + (1.f - beta) * o4.w;
    *(float4*)&out[node * 128 + lane * 4] = r;
}

// ---------------------------------------------------------------------------
extern "C" void kernel_launch(void* const* d_in, const int* in_sizes, int n_in,
                              void* d_out, int out_size)
{
    const float* x         = (const float*)d_in[0];
    const float* edge_attr = (const float*)d_in[1];
    const int*   edge_idx  = (const int*)  d_in[2];
    const float* Wq = (const float*)d_in[3];
    const float* bq = (const float*)d_in[4];
    const float* Wk = (const float*)d_in[5];
    const float* bk = (const float*)d_in[6];
    const float* Wv = (const float*)d_in[7];
    const float* bv = (const float*)d_in[8];
    const float* We = (const float*)d_in[9];
    const float* Ws = (const float*)d_in[10];
    const float* bs = (const float*)d_in[11];
    const float* Wbeta = (const float*)d_in[12];
    float* out = (float*)d_out;

    int n = in_sizes[0] / 128;
    int e = in_sizes[1] / 16;
    const int* row  = edge_idx;      // destination nodes
    const int* colv = edge_idx + e;  // source nodes

    cudaFuncSetAttribute(proj_mma, cudaFuncAttributeMaxDynamicSharedMemorySize,
                         PROJ_SMEM);

    prepack_kernel<<<288 + (MAXN + 255) / 256, 256>>>(Wq, Wk, Wv, Ws, We, bq);
    fill_buckets<<<(e + 255) / 256, 256>>>(row, colv, e);
    proj_mma<<<(n + 127) / 128, 256, PROJ_SMEM>>>(x, bq, bk, bv, bs, n);
    agg_kernel<<<((long long)n * 32 + 255) / 256, 256>>>(edge_attr, Wbeta, out, n);
}

// round 5
// speedup vs baseline: 1.6679x; 1.0399x over previous
#include <cuda_runtime.h>
#include <cuda_bf16.h>
#include <cuda_fp16.h>
#include <cstdint>

// ---------------------------------------------------------------------------
// TransformerConv: N=100000 nodes, E=1600000 edges, IN=128, H=4, C=32, ED=16
//
// sm_103 base target (NO tcgen05 — harness PTX is .target sm_103):
//   1) pack_w     : W{q,k,v,skip} -> fp16 hi/lo, transposed [512 x 128]
//   2) fold_zero  : Wg = fold(Wq, We) -> rows 512..575; zero d_count
//   3) fill_buckets: bucket {edge,src} pairs by destination node
//   4) proj_mma   : q,g (fp32) + packed fp16 k,v + skip via mma.sync fp16
//                   2-MMA hi/lo split (x_hi*W_hi + x_hi*W_lo), fp32 accum
//   5) agg_kernel : warp-per-dst-node, batched-shfl + prefetch-4 gathers,
//                   softmax aggregation + gated skip fused
// ---------------------------------------------------------------------------

#define MAXN 100096
#define BCAP 96   // per-node bucket capacity (Poisson(16) max ~36; 96 is safe)

__device__ float d_qbuf[MAXN * 128];
__device__ float d_sbuf[MAXN * 128];
__device__ float d_gbuf[MAXN * 64];
__device__ uint4 d_kv[MAXN * 32];      // per node: 32 lanes x 16B {k4 half, v4 half}
__device__ int   d_count[MAXN];
__device__ int2  d_bucket[MAXN * BCAP];   // {edge id, src node}
__device__ __half d_Bhi[576 * 128];    // W^T hi, n-major rows, k cols (+Wg)
__device__ __half d_Blo[576 * 128];    // W^T lo
__device__ float d_bg[64];             // bias for folded g projection

// ============================ helpers ======================================
__device__ __forceinline__ uint32_t smem_u32(const void* p) {
    uint32_t a;
    asm("{ .reg .u64 t; cvta.to.shared.u64 t, %1; cvt.u32.u64 %0, t; }"
        : "=r"(a) : "l"(p));
    return a;
}
__device__ __forceinline__ void ldm_x4(uint32_t& r0, uint32_t& r1,
                                       uint32_t& r2, uint32_t& r3, uint32_t addr) {
    asm volatile("ldmatrix.sync.aligned.m8n8.x4.shared.b16 {%0,%1,%2,%3}, [%4];"
                 : "=r"(r0), "=r"(r1), "=r"(r2), "=r"(r3) : "r"(addr));
}
__device__ __forceinline__ void ldm_x2(uint32_t& r0, uint32_t& r1, uint32_t addr) {
    asm volatile("ldmatrix.sync.aligned.m8n8.x2.shared.b16 {%0,%1}, [%2];"
                 : "=r"(r0), "=r"(r1) : "r"(addr));
}
__device__ __forceinline__ void mma_f16(float* c, const uint32_t* a,
                                        uint32_t b0, uint32_t b1) {
    asm volatile(
        "mma.sync.aligned.m16n8k16.row.col.f32.f16.f16.f32 "
        "{%0,%1,%2,%3}, {%4,%5,%6,%7}, {%8,%9}, {%0,%1,%2,%3};"
        : "+f"(c[0]), "+f"(c[1]), "+f"(c[2]), "+f"(c[3])
        : "r"(a[0]), "r"(a[1]), "r"(a[2]), "r"(a[3]), "r"(b0), "r"(b1));
}

// ---------------------------------------------------------------------------
// pack_w: W[k][col] (4 matrices) -> Bhi/Blo[n=512 rows][k=128] fp16 hi/lo
// ---------------------------------------------------------------------------
__global__ void __launch_bounds__(256)
pack_w(const float* __restrict__ Wq, const float* __restrict__ Wk,
       const float* __restrict__ Wv, const float* __restrict__ Ws)
{
    int i = blockIdx.x * 256 + threadIdx.x;   // 65536 elements
    int k = i >> 9, nn = i & 511;
    int w = nn >> 7, c = nn & 127;
    const float* W = (w == 0) ? Wq : (w == 1) ? Wk : (w == 2) ? Wv : Ws;
    float v = W[k * 128 + c];
    __half h = __float2half_rn(v);
    d_Bhi[nn * 128 + k] = h;
    d_Blo[nn * 128 + k] = __float2half_rn(v - __half2float(h));
}

// ---------------------------------------------------------------------------
// fold_zero: blocks [0,32): Wg fold; [32, ...): zero d_count
// ---------------------------------------------------------------------------
__global__ void __launch_bounds__(256)
fold_zero(const float* __restrict__ Wq, const float* __restrict__ We,
          const float* __restrict__ bq)
{
    int b = blockIdx.x, tid = threadIdx.x;
    if (b < 32) {
        int t = b * 256 + tid;               // 8192: (i, o)
        int i = t >> 6, o = t & 63;
        int h = o >> 4, d = o & 15;
        float s = 0.f;
#pragma unroll
        for (int c = 0; c < 32; ++c)
            s += Wq[i * 128 + h * 32 + c] * We[d * 128 + h * 32 + c];
        __half hh = __float2half_rn(s);
        d_Bhi[(512 + o) * 128 + i] = hh;
        d_Blo[(512 + o) * 128 + i] = __float2half_rn(s - __half2float(hh));
        if (i == 0) {
            float sb = 0.f;
#pragma unroll
            for (int c = 0; c < 32; ++c)
                sb += bq[h * 32 + c] * We[d * 128 + h * 32 + c];
            d_bg[o] = sb;
        }
    } else {
        int i = (b - 32) * 256 + tid;
        if (i < MAXN) d_count[i] = 0;
    }
}

// ---------------------------------------------------------------------------
// Edge bucketing: store {edge, src} pairs (kills a dependent load in agg)
// ---------------------------------------------------------------------------
__global__ void __launch_bounds__(256)
fill_buckets(const int* __restrict__ row, const int* __restrict__ colv, int e)
{
    int i = blockIdx.x * blockDim.x + threadIdx.x;
    if (i >= e) return;
    int dst = row[i];
    int src = colv[i];
    int pos = atomicAdd(&d_count[dst], 1);
    if (pos < BCAP) d_bucket[dst * BCAP + pos] = make_int2(i, src);
}

// ---------------------------------------------------------------------------
// Projection via mma.sync fp16: per CTA M=128 tile, 5 N-chunks (q,k,v,skip,g)
// 2-MMA hi/lo: A = x_hi fp16; result = A*Bhi + A*Blo = x_hi * W (fp32 accum)
// smem rows padded to 136 halves (272B) -> conflict-free ldmatrix
// ---------------------------------------------------------------------------
#define ASTR 136
#define PROJ_SMEM (3 * 128 * ASTR * 2)

__global__ void __launch_bounds__(256, 1)
proj_mma(const float* __restrict__ x,
         const float* __restrict__ bq, const float* __restrict__ bk,
         const float* __restrict__ bv, const float* __restrict__ bs,
         int n)
{
    extern __shared__ __align__(16) char smem[];
    ushort* sA    = (ushort*)smem;                 // [128][ASTR]
    ushort* sB_hi = sA + 128 * ASTR;
    ushort* sB_lo = sB_hi + 128 * ASTR;

    int tid = threadIdx.x, lane = tid & 31, wid = tid >> 5;
    int row0 = blockIdx.x * 128;

    // Stage x tile -> fp16
    for (int i = tid; i < 128 * 32; i += 256) {
        int r = i >> 5, c4 = i & 31;
        int node = row0 + r;
        float4 xv = (node < n) ? *(const float4*)&x[node * 128 + c4 * 4]
                               : make_float4(0.f, 0.f, 0.f, 0.f);
        __half2 h01 = __floats2half2_rn(xv.x, xv.y);
        __half2 h23 = __floats2half2_rn(xv.z, xv.w);
        *(uint2*)&sA[r * ASTR + c4 * 4] =
            make_uint2(*(uint32_t*)&h01, *(uint32_t*)&h23);
    }

    uint32_t uA = smem_u32(sA);
    uint32_t uBhi = smem_u32(sB_hi), uBlo = smem_u32(sB_lo);

    const float* biasl[4] = {bq, bk, bv, bs};
    ushort* kvs = (ushort*)d_kv;

    for (int nc = 0; nc < 5; ++nc) {
        int NF = (nc == 4) ? 8 : 16;             // g chunk is N=64
        __syncthreads();
        // Stage W chunk [NF*8 n-rows][128 k] hi/lo
        for (int i = tid; i < NF * 8 * 16; i += 256) {
            int r = i >> 4, c8 = i & 15;
            int gidx = (nc * 128 + r) * 128 + c8 * 8;
            *(uint4*)&sB_hi[r * ASTR + c8 * 8] = *(const uint4*)&d_Bhi[gidx];
            *(uint4*)&sB_lo[r * ASTR + c8 * 8] = *(const uint4*)&d_Blo[gidx];
        }
        __syncthreads();

        float acc[16][4];
#pragma unroll
        for (int f = 0; f < 16; ++f)
#pragma unroll
            for (int j = 0; j < 4; ++j) acc[f][j] = 0.f;

        uint32_t a_row = (uint32_t)(wid * 16 + (lane & 15));
        uint32_t a_koff = (uint32_t)((lane >> 4) * 8);
        uint32_t b_row = (uint32_t)(lane & 7);
        uint32_t b_koff = (uint32_t)(((lane >> 3) & 1) * 8);

#pragma unroll
        for (int ks = 0; ks < 8; ++ks) {
            uint32_t aoff = (a_row * ASTR + ks * 16 + a_koff) * 2;
            uint32_t a[4];
            ldm_x4(a[0], a[1], a[2], a[3], uA + aoff);
#pragma unroll
            for (int nf = 0; nf < 16; ++nf) {
                if (nf >= NF) break;
                uint32_t boff = ((nf * 8 + b_row) * ASTR + ks * 16 + b_koff) * 2;
                uint32_t bh0, bh1, bl0, bl1;
                ldm_x2(bh0, bh1, uBhi + boff);
                ldm_x2(bl0, bl1, uBlo + boff);
                mma_f16(acc[nf], a, bh0, bh1);
                mma_f16(acc[nf], a, bl0, bl1);
            }
        }

        // Epilogue
        int r_base = row0 + wid * 16 + (lane >> 2);
        if (nc == 4) {
#pragma unroll
            for (int nf = 0; nf < 8; ++nf) {
                int cn = nf * 8 + (lane & 3) * 2;
                float b0 = d_bg[cn], b1 = d_bg[cn + 1];
#pragma unroll
                for (int half = 0; half < 2; ++half) {
                    int node = r_base + half * 8;
                    if (node >= n) continue;
                    *(float2*)&d_gbuf[node * 64 + cn] =
                        make_float2(acc[nf][half * 2] + b0, acc[nf][half * 2 + 1] + b1);
                }
            }
        } else {
            const float* bias = biasl[nc];
#pragma unroll
            for (int nf = 0; nf < 16; ++nf) {
                int cn = nf * 8 + (lane & 3) * 2;
                float b0 = __ldg(&bias[cn]), b1 = __ldg(&bias[cn + 1]);
#pragma unroll
                for (int half = 0; half < 2; ++half) {
                    int node = r_base + half * 8;
                    if (node >= n) continue;
                    float v0 = acc[nf][half * 2 + 0] + b0;
                    float v1 = acc[nf][half * 2 + 1] + b1;
                    if (nc == 0) {
                        *(float2*)&d_qbuf[node * 128 + cn] = make_float2(v0, v1);
                    } else if (nc == 3) {
                        *(float2*)&d_sbuf[node * 128 + cn] = make_float2(v0, v1);
                    } else {
                        __half2 hh = __floats2half2_rn(v0, v1);
                        uint32_t idx = (uint32_t)node * 256 + ((cn >> 2) << 3)
                                     + (cn & 3) + (nc == 2 ? 4 : 0);
                        *(uint32_t*)&kvs[idx] = *(uint32_t*)&hh;
                    }
                }
            }
        }
    }
}

// ---------------------------------------------------------------------------
// Warp-per-node softmax aggregation + gated skip.
// Batched {edge,src} preload (coalesced) + shfl broadcast + prefetch-4.
// ---------------------------------------------------------------------------
__global__ void __launch_bounds__(256)
agg_kernel(const float* __restrict__ edge_attr,
           const float* __restrict__ Wbeta,
           float* __restrict__ out, int n)
{
    int warp = (blockIdx.x * blockDim.x + threadIdx.x) >> 5;
    int lane = threadIdx.x & 31;
    if (warp >= n) return;
    int node = warp;
    int l8 = lane & 7;
    int h = lane >> 3;

    float4 q4 = *(const float4*)&d_qbuf[node * 128 + lane * 4];
    float2 g2 = *(const float2*)&d_gbuf[node * 64 + h * 16 + l8 * 2];

    int deg = d_count[node];
    if (deg > BCAP) deg = BCAP;

    float4 acc = make_float4(0.f, 0.f, 0.f, 0.f);
    float den = 0.f;

    for (int j0 = 0; j0 < deg; j0 += 32) {
        int jb = min(32, deg - j0);
        int e_l = 0, s_l = 0;
        if (lane < jb) {
            int2 es = d_bucket[node * BCAP + j0 + lane];
            e_l = es.x; s_l = es.y;
        }
        int j = 0;
        for (; j + 4 <= jb; j += 4) {
            uint4 kvv[4];
            float2 ea[4];
#pragma unroll
            for (int t = 0; t < 4; ++t) {
                int e   = __shfl_sync(0xffffffffu, e_l, j + t);
                int src = __shfl_sync(0xffffffffu, s_l, j + t);
                kvv[t] = __ldg(&d_kv[src * 32 + lane]);
                ea[t]  = *(const float2*)&edge_attr[e * 16 + l8 * 2];
            }
#pragma unroll
            for (int t = 0; t < 4; ++t) {
                float2 k01 = __half22float2(*(__half2*)&kvv[t].x);
                float2 k23 = __half22float2(*(__half2*)&kvv[t].y);
                float2 v01 = __half22float2(*(__half2*)&kvv[t].z);
                float2 v23 = __half22float2(*(__half2*)&kvv[t].w);
                float dot = q4.x * k01.x + q4.y * k01.y + q4.z * k23.x + q4.w * k23.y
                          + g2.x * ea[t].x + g2.y * ea[t].y;
                dot += __shfl_xor_sync(0xffffffffu, dot, 1);
                dot += __shfl_xor_sync(0xffffffffu, dot, 2);
                dot += __shfl_xor_sync(0xffffffffu, dot, 4);
                float ex = __expf(dot * 0.17677669529663687f);  // 1/sqrt(32)
                den += ex;
                acc.x += ex * v01.x; acc.y += ex * v01.y;
                acc.z += ex * v23.x; acc.w += ex * v23.y;
            }
        }
        for (; j < jb; ++j) {
            int e   = __shfl_sync(0xffffffffu, e_l, j);
            int src = __shfl_sync(0xffffffffu, s_l, j);
            uint4 kvv = __ldg(&d_kv[src * 32 + lane]);
            float2 ea = *(const float2*)&edge_attr[e * 16 + l8 * 2];
            float2 k01 = __half22float2(*(__half2*)&kvv.x);
            float2 k23 = __half22float2(*(__half2*)&kvv.y);
            float2 v01 = __half22float2(*(__half2*)&kvv.z);
            float2 v23 = __half22float2(*(__half2*)&kvv.w);
            float dot = q4.x * k01.x + q4.y * k01.y + q4.z * k23.x + q4.w * k23.y
                      + g2.x * ea.x + g2.y * ea.y;
            dot += __shfl_xor_sync(0xffffffffu, dot, 1);
            dot += __shfl_xor_sync(0xffffffffu, dot, 2);
            dot += __shfl_xor_sync(0xffffffffu, dot, 4);
            float ex = __expf(dot * 0.17677669529663687f);
            den += ex;
            acc.x += ex * v01.x; acc.y += ex * v01.y;
            acc.z += ex * v23.x; acc.w += ex * v23.y;
        }
    }

    float inv = 1.f / (den + 1e-16f);
    float4 o4 = make_float4(acc.x * inv, acc.y * inv, acc.z * inv, acc.w * inv);
    float4 xs4 = *(const float4*)&d_sbuf[node * 128 + lane * 4];

    // beta = sigmoid(out.(Wb0+Wb2) + xs.(Wb1-Wb2))
    float4 wb0 = *(const float4*)&Wbeta[lane * 4];
    float4 wb1 = *(const float4*)&Wbeta[128 + lane * 4];
    float4 wb2 = *(const float4*)&Wbeta[256 + lane * 4];
    float s = o4.x * (wb0.x + wb2.x) + o4.y * (wb0.y + wb2.y)
            + o4.z * (wb0.z + wb2.z) + o4.w * (wb0.w + wb2.w)
            + xs4.x * (wb1.x - wb2.x) + xs4.y * (wb1.y - wb2.y)
            + xs4.z * (wb1.z - wb2.z) + xs4.w * (wb1.w - wb2.w);
    s += __shfl_xor_sync(0xffffffffu, s, 1);
    s += __shfl_xor_sync(0xffffffffu, s, 2);
    s += __shfl_xor_sync(0xffffffffu, s, 4);
    s += __shfl_xor_sync(0xffffffffu, s, 8);
    s += __shfl_xor_sync(0xffffffffu, s, 16);
    float beta = 1.f / (1.f + __expf(-s));

    float4 r;
    r.x = beta * xs4.x + (1.f - beta) * o4.x;
    r.y = beta * xs4.y + (1.f - beta) * o4.y;
    r.z = beta * xs4.z + (1.f - beta) * o4.z;
    r.w = beta * xs4.w + (1.f - beta) * o4.w;
    *(float4*)&out[node * 128 + lane * 4] = r;
}

// ---------------------------------------------------------------------------
extern "C" void kernel_launch(void* const* d_in, const int* in_sizes, int n_in,
                              void* d_out, int out_size)
{
    const float* x         = (const float*)d_in[0];
    const float* edge_attr = (const float*)d_in[1];
    const int*   edge_idx  = (const int*)  d_in[2];
    const float* Wq = (const float*)d_in[3];
    const float* bq = (const float*)d_in[4];
    const float* Wk = (const float*)d_in[5];
    const float* bk = (const float*)d_in[6];
    const float* Wv = (const float*)d_in[7];
    const float* bv = (const float*)d_in[8];
    const float* We = (const float*)d_in[9];
    const float* Ws = (const float*)d_in[10];
    const float* bs = (const float*)d_in[11];
    const float* Wbeta = (const float*)d_in[12];
    float* out = (float*)d_out;

    int n = in_sizes[0] / 128;
    int e = in_sizes[1] / 16;
    const int* row  = edge_idx;      // destination nodes
    const int* colv = edge_idx + e;  // source nodes

    cudaFuncSetAttribute(proj_mma, cudaFuncAttributeMaxDynamicSharedMemorySize,
                         PROJ_SMEM);

    pack_w<<<256, 256>>>(Wq, Wk, Wv, Ws);
    fold_zero<<<32 + (MAXN + 255) / 256, 256>>>(Wq, We, bq);
    fill_buckets<<<(e + 255) / 256, 256>>>(row, colv, e);
    proj_mma<<<(n + 127) / 128, 256, PROJ_SMEM>>>(x, bq, bk, bv, bs, n);
    agg_kernel<<<((long long)n * 32 + 255) / 256, 256>>>(edge_attr, Wbeta, out, n);
}

// round 6
// speedup vs baseline: 2.1451x; 1.2861x over previous
#include <cuda_runtime.h>
#include <cuda_bf16.h>
#include <cuda_fp16.h>
#include <cstdint>

// ---------------------------------------------------------------------------
// TransformerConv: N=100000 nodes, E=1600000 edges, IN=128, H=4, C=32, ED=16
//
// sm_103 base target (NO tcgen05 — harness PTX is .target sm_103):
//   1) pack_w     : W{q,k,v,skip} -> fp16, transposed [512 x 128]
//   2) fold_zero  : Wg = fold(Wq, We) -> rows 512..575; zero d_count
//   3) fill_buckets: bucket {edge,src} pairs by destination node
//   4) proj_mma   : single fp16 mma.sync (x_h * W_h), fp32 accum,
//                   M=256 tile / 512 threads for latency hiding
//   5) agg_kernel : warp-per-dst-node, batched-shfl + prefetch-4 gathers,
//                   softmax aggregation + gated skip fused
// ---------------------------------------------------------------------------

#define MAXN 100096
#define BCAP 96   // per-node bucket capacity (Poisson(16) max ~36; 96 is safe)

__device__ float d_qbuf[MAXN * 128];
__device__ float d_sbuf[MAXN * 128];
__device__ float d_gbuf[MAXN * 64];
__device__ uint4 d_kv[MAXN * 32];      // per node: 32 lanes x 16B {k4 half, v4 half}
__device__ int   d_count[MAXN];
__device__ int2  d_bucket[MAXN * BCAP];   // {edge id, src node}
__device__ __half d_B[576 * 128];      // W^T fp16, n-major rows, k cols (+Wg)
__device__ float d_bg[64];             // bias for folded g projection

// ============================ helpers ======================================
__device__ __forceinline__ uint32_t smem_u32(const void* p) {
    uint32_t a;
    asm("{ .reg .u64 t; cvta.to.shared.u64 t, %1; cvt.u32.u64 %0, t; }"
        : "=r"(a) : "l"(p));
    return a;
}
__device__ __forceinline__ void ldm_x4(uint32_t& r0, uint32_t& r1,
                                       uint32_t& r2, uint32_t& r3, uint32_t addr) {
    asm volatile("ldmatrix.sync.aligned.m8n8.x4.shared.b16 {%0,%1,%2,%3}, [%4];"
                 : "=r"(r0), "=r"(r1), "=r"(r2), "=r"(r3) : "r"(addr));
}
__device__ __forceinline__ void ldm_x2(uint32_t& r0, uint32_t& r1, uint32_t addr) {
    asm volatile("ldmatrix.sync.aligned.m8n8.x2.shared.b16 {%0,%1}, [%2];"
                 : "=r"(r0), "=r"(r1) : "r"(addr));
}
__device__ __forceinline__ void mma_f16(float* c, const uint32_t* a,
                                        uint32_t b0, uint32_t b1) {
    asm volatile(
        "mma.sync.aligned.m16n8k16.row.col.f32.f16.f16.f32 "
        "{%0,%1,%2,%3}, {%4,%5,%6,%7}, {%8,%9}, {%0,%1,%2,%3};"
        : "+f"(c[0]), "+f"(c[1]), "+f"(c[2]), "+f"(c[3])
        : "r"(a[0]), "r"(a[1]), "r"(a[2]), "r"(a[3]), "r"(b0), "r"(b1));
}

// ---------------------------------------------------------------------------
// pack_w: W[k][col] (4 matrices) -> d_B[n=512 rows][k=128] fp16
// ---------------------------------------------------------------------------
__global__ void __launch_bounds__(256)
pack_w(const float* __restrict__ Wq, const float* __restrict__ Wk,
       const float* __restrict__ Wv, const float* __restrict__ Ws)
{
    int i = blockIdx.x * 256 + threadIdx.x;   // 65536 elements
    int k = i >> 9, nn = i & 511;
    int w = nn >> 7, c = nn & 127;
    const float* W = (w == 0) ? Wq : (w == 1) ? Wk : (w == 2) ? Wv : Ws;
    d_B[nn * 128 + k] = __float2half_rn(W[k * 128 + c]);
}

// ---------------------------------------------------------------------------
// fold_zero: blocks [0,32): Wg fold; [32, ...): zero d_count
// ---------------------------------------------------------------------------
__global__ void __launch_bounds__(256)
fold_zero(const float* __restrict__ Wq, const float* __restrict__ We,
          const float* __restrict__ bq)
{
    int b = blockIdx.x, tid = threadIdx.x;
    if (b < 32) {
        int t = b * 256 + tid;               // 8192: (i, o)
        int i = t >> 6, o = t & 63;
        int h = o >> 4, d = o & 15;
        float s = 0.f;
#pragma unroll
        for (int c = 0; c < 32; ++c)
            s += Wq[i * 128 + h * 32 + c] * We[d * 128 + h * 32 + c];
        d_B[(512 + o) * 128 + i] = __float2half_rn(s);
        if (i == 0) {
            float sb = 0.f;
#pragma unroll
            for (int c = 0; c < 32; ++c)
                sb += bq[h * 32 + c] * We[d * 128 + h * 32 + c];
            d_bg[o] = sb;
        }
    } else {
        int i = (b - 32) * 256 + tid;
        if (i < MAXN) d_count[i] = 0;
    }
}

// ---------------------------------------------------------------------------
// Edge bucketing: store {edge, src} pairs (kills a dependent load in agg)
// ---------------------------------------------------------------------------
__global__ void __launch_bounds__(256)
fill_buckets(const int* __restrict__ row, const int* __restrict__ colv, int e)
{
    int i = blockIdx.x * blockDim.x + threadIdx.x;
    if (i >= e) return;
    int dst = row[i];
    int src = colv[i];
    int pos = atomicAdd(&d_count[dst], 1);
    if (pos < BCAP) d_bucket[dst * BCAP + pos] = make_int2(i, src);
}

// ---------------------------------------------------------------------------
// Projection via single fp16 mma.sync: per CTA M=256 tile / 512 threads,
// 5 N-chunks (q,k,v,skip,g). smem rows padded to 136 halves -> conflict-free.
// ---------------------------------------------------------------------------
#define ASTR 136
#define PROJ_SMEM ((256 + 128) * ASTR * 2)

__global__ void __launch_bounds__(512, 1)
proj_mma(const float* __restrict__ x,
         const float* __restrict__ bq, const float* __restrict__ bk,
         const float* __restrict__ bv, const float* __restrict__ bs,
         int n)
{
    extern __shared__ __align__(16) char smem[];
    ushort* sA = (ushort*)smem;                 // [256][ASTR]
    ushort* sB = sA + 256 * ASTR;               // [128][ASTR]

    int tid = threadIdx.x, lane = tid & 31, wid = tid >> 5;
    int row0 = blockIdx.x * 256;

    // Stage x tile -> fp16
    for (int i = tid; i < 256 * 32; i += 512) {
        int r = i >> 5, c4 = i & 31;
        int node = row0 + r;
        float4 xv = (node < n) ? *(const float4*)&x[node * 128 + c4 * 4]
                               : make_float4(0.f, 0.f, 0.f, 0.f);
        __half2 h01 = __floats2half2_rn(xv.x, xv.y);
        __half2 h23 = __floats2half2_rn(xv.z, xv.w);
        *(uint2*)&sA[r * ASTR + c4 * 4] =
            make_uint2(*(uint32_t*)&h01, *(uint32_t*)&h23);
    }

    uint32_t uA = smem_u32(sA);
    uint32_t uB = smem_u32(sB);

    const float* biasl[4] = {bq, bk, bv, bs};
    ushort* kvs = (ushort*)d_kv;

    for (int nc = 0; nc < 5; ++nc) {
        int NF = (nc == 4) ? 8 : 16;             // g chunk is N=64
        __syncthreads();
        // Stage W chunk [NF*8 n-rows][128 k]
        for (int i = tid; i < NF * 8 * 16; i += 512) {
            int r = i >> 4, c8 = i & 15;
            *(uint4*)&sB[r * ASTR + c8 * 8] =
                *(const uint4*)&d_B[(nc * 128 + r) * 128 + c8 * 8];
        }
        __syncthreads();

        float acc[16][4];
#pragma unroll
        for (int f = 0; f < 16; ++f)
#pragma unroll
            for (int j = 0; j < 4; ++j) acc[f][j] = 0.f;

        uint32_t a_row = (uint32_t)(wid * 16 + (lane & 15));
        uint32_t a_koff = (uint32_t)((lane >> 4) * 8);
        uint32_t b_row = (uint32_t)(lane & 7);
        uint32_t b_koff = (uint32_t)(((lane >> 3) & 1) * 8);

#pragma unroll
        for (int ks = 0; ks < 8; ++ks) {
            uint32_t aoff = (a_row * ASTR + ks * 16 + a_koff) * 2;
            uint32_t a[4];
            ldm_x4(a[0], a[1], a[2], a[3], uA + aoff);
#pragma unroll
            for (int nf = 0; nf < 16; ++nf) {
                if (nf >= NF) break;
                uint32_t boff = ((nf * 8 + b_row) * ASTR + ks * 16 + b_koff) * 2;
                uint32_t b0, b1;
                ldm_x2(b0, b1, uB + boff);
                mma_f16(acc[nf], a, b0, b1);
            }
        }

        // Epilogue
        int r_base = row0 + wid * 16 + (lane >> 2);
        if (nc == 4) {
#pragma unroll
            for (int nf = 0; nf < 8; ++nf) {
                int cn = nf * 8 + (lane & 3) * 2;
                float b0 = d_bg[cn], b1 = d_bg[cn + 1];
#pragma unroll
                for (int half = 0; half < 2; ++half) {
                    int node = r_base + half * 8;
                    if (node >= n) continue;
                    *(float2*)&d_gbuf[node * 64 + cn] =
                        make_float2(acc[nf][half * 2] + b0, acc[nf][half * 2 + 1] + b1);
                }
            }
        } else {
            const float* bias = biasl[nc];
#pragma unroll
            for (int nf = 0; nf < 16; ++nf) {
                int cn = nf * 8 + (lane & 3) * 2;
                float b0 = __ldg(&bias[cn]), b1 = __ldg(&bias[cn + 1]);
#pragma unroll
                for (int half = 0; half < 2; ++half) {
                    int node = r_base + half * 8;
                    if (node >= n) continue;
                    float v0 = acc[nf][half * 2 + 0] + b0;
                    float v1 = acc[nf][half * 2 + 1] + b1;
                    if (nc == 0) {
                        *(float2*)&d_qbuf[node * 128 + cn] = make_float2(v0, v1);
                    } else if (nc == 3) {
                        *(float2*)&d_sbuf[node * 128 + cn] = make_float2(v0, v1);
                    } else {
                        __half2 hh = __floats2half2_rn(v0, v1);
                        uint32_t idx = (uint32_t)node * 256 + ((cn >> 2) << 3)
                                     + (cn & 3) + (nc == 2 ? 4 : 0);
                        *(uint32_t*)&kvs[idx] = *(uint32_t*)&hh;
                    }
                }
            }
        }
    }
}

// ---------------------------------------------------------------------------
// Warp-per-node softmax aggregation + gated skip.
// Batched {edge,src} preload (coalesced) + shfl broadcast + prefetch-4.
// ---------------------------------------------------------------------------
__global__ void __launch_bounds__(256)
agg_kernel(const float* __restrict__ edge_attr,
           const float* __restrict__ Wbeta,
           float* __restrict__ out, int n)
{
    int warp = (blockIdx.x * blockDim.x + threadIdx.x) >> 5;
    int lane = threadIdx.x & 31;
    if (warp >= n) return;
    int node = warp;
    int l8 = lane & 7;
    int h = lane >> 3;

    float4 q4 = *(const float4*)&d_qbuf[node * 128 + lane * 4];
    float2 g2 = *(const float2*)&d_gbuf[node * 64 + h * 16 + l8 * 2];

    int deg = d_count[node];
    if (deg > BCAP) deg = BCAP;

    float4 acc = make_float4(0.f, 0.f, 0.f, 0.f);
    float den = 0.f;

    for (int j0 = 0; j0 < deg; j0 += 32) {
        int jb = min(32, deg - j0);
        int e_l = 0, s_l = 0;
        if (lane < jb) {
            int2 es = d_bucket[node * BCAP + j0 + lane];
            e_l = es.x; s_l = es.y;
        }
        int j = 0;
        for (; j + 4 <= jb; j += 4) {
            uint4 kvv[4];
            float2 ea[4];
#pragma unroll
            for (int t = 0; t < 4; ++t) {
                int e   = __shfl_sync(0xffffffffu, e_l, j + t);
                int src = __shfl_sync(0xffffffffu, s_l, j + t);
                kvv[t] = __ldg(&d_kv[src * 32 + lane]);
                ea[t]  = *(const float2*)&edge_attr[e * 16 + l8 * 2];
            }
#pragma unroll
            for (int t = 0; t < 4; ++t) {
                float2 k01 = __half22float2(*(__half2*)&kvv[t].x);
                float2 k23 = __half22float2(*(__half2*)&kvv[t].y);
                float2 v01 = __half22float2(*(__half2*)&kvv[t].z);
                float2 v23 = __half22float2(*(__half2*)&kvv[t].w);
                float dot = q4.x * k01.x + q4.y * k01.y + q4.z * k23.x + q4.w * k23.y
                          + g2.x * ea[t].x + g2.y * ea[t].y;
                dot += __shfl_xor_sync(0xffffffffu, dot, 1);
                dot += __shfl_xor_sync(0xffffffffu, dot, 2);
                dot += __shfl_xor_sync(0xffffffffu, dot, 4);
                float ex = __expf(dot * 0.17677669529663687f);  // 1/sqrt(32)
                den += ex;
                acc.x += ex * v01.x; acc.y += ex * v01.y;
                acc.z += ex * v23.x; acc.w += ex * v23.y;
            }
        }
        for (; j < jb; ++j) {
            int e   = __shfl_sync(0xffffffffu, e_l, j);
            int src = __shfl_sync(0xffffffffu, s_l, j);
            uint4 kvv = __ldg(&d_kv[src * 32 + lane]);
            float2 ea = *(const float2*)&edge_attr[e * 16 + l8 * 2];
            float2 k01 = __half22float2(*(__half2*)&kvv.x);
            float2 k23 = __half22float2(*(__half2*)&kvv.y);
            float2 v01 = __half22float2(*(__half2*)&kvv.z);
            float2 v23 = __half22float2(*(__half2*)&kvv.w);
            float dot = q4.x * k01.x + q4.y * k01.y + q4.z * k23.x + q4.w * k23.y
                      + g2.x * ea.x + g2.y * ea.y;
            dot += __shfl_xor_sync(0xffffffffu, dot, 1);
            dot += __shfl_xor_sync(0xffffffffu, dot, 2);
            dot += __shfl_xor_sync(0xffffffffu, dot, 4);
            float ex = __expf(dot * 0.17677669529663687f);
            den += ex;
            acc.x += ex * v01.x; acc.y += ex * v01.y;
            acc.z += ex * v23.x; acc.w += ex * v23.y;
        }
    }

    float inv = 1.f / (den + 1e-16f);
    float4 o4 = make_float4(acc.x * inv, acc.y * inv, acc.z * inv, acc.w * inv);
    float4 xs4 = *(const float4*)&d_sbuf[node * 128 + lane * 4];

    // beta = sigmoid(out.(Wb0+Wb2) + xs.(Wb1-Wb2))
    float4 wb0 = *(const float4*)&Wbeta[lane * 4];
    float4 wb1 = *(const float4*)&Wbeta[128 + lane * 4];
    float4 wb2 = *(const float4*)&Wbeta[256 + lane * 4];
    float s = o4.x * (wb0.x + wb2.x) + o4.y * (wb0.y + wb2.y)
            + o4.z * (wb0.z + wb2.z) + o4.w * (wb0.w + wb2.w)
            + xs4.x * (wb1.x - wb2.x) + xs4.y * (wb1.y - wb2.y)
            + xs4.z * (wb1.z - wb2.z) + xs4.w * (wb1.w - wb2.w);
    s += __shfl_xor_sync(0xffffffffu, s, 1);
    s += __shfl_xor_sync(0xffffffffu, s, 2);
    s += __shfl_xor_sync(0xffffffffu, s, 4);
    s += __shfl_xor_sync(0xffffffffu, s, 8);
    s += __shfl_xor_sync(0xffffffffu, s, 16);
    float beta = 1.f / (1.f + __expf(-s));

    float4 r;
    r.x = beta * xs4.x + (1.f - beta) * o4.x;
    r.y = beta * xs4.y + (1.f - beta) * o4.y;
    r.z = beta * xs4.z + (1.f - beta) * o4.z;
    r.w = beta * xs4.w + (1.f - beta) * o4.w;
    *(float4*)&out[node * 128 + lane * 4] = r;
}

// ---------------------------------------------------------------------------
extern "C" void kernel_launch(void* const* d_in, const int* in_sizes, int n_in,
                              void* d_out, int out_size)
{
    const float* x         = (const float*)d_in[0];
    const float* edge_attr = (const float*)d_in[1];
    const int*   edge_idx  = (const int*)  d_in[2];
    const float* Wq = (const float*)d_in[3];
    const float* bq = (const float*)d_in[4];
    const float* Wk = (const float*)d_in[5];
    const float* bk = (const float*)d_in[6];
    const float* Wv = (const float*)d_in[7];
    const float* bv = (const float*)d_in[8];
    const float* We = (const float*)d_in[9];
    const float* Ws = (const float*)d_in[10];
    const float* bs = (const float*)d_in[11];
    const float* Wbeta = (const float*)d_in[12];
    float* out = (float*)d_out;

    int n = in_sizes[0] / 128;
    int e = in_sizes[1] / 16;
    const int* row  = edge_idx;      // destination nodes
    const int* colv = edge_idx + e;  // source nodes

    cudaFuncSetAttribute(proj_mma, cudaFuncAttributeMaxDynamicSharedMemorySize,
                         PROJ_SMEM);

    pack_w<<<256, 256>>>(Wq, Wk, Wv, Ws);
    fold_zero<<<32 + (MAXN + 255) / 256, 256>>>(Wq, We, bq);
    fill_buckets<<<(e + 255) / 256, 256>>>(row, colv, e);
    proj_mma<<<(n + 255) / 256, 512, PROJ_SMEM>>>(x, bq, bk, bv, bs, n);
    agg_kernel<<<((long long)n * 32 + 255) / 256, 256>>>(edge_attr, Wbeta, out, n);
}

// round 7
// speedup vs baseline: 2.1970x; 1.0242x over previous
#include <cuda_runtime.h>
#include <cuda_bf16.h>
#include <cuda_fp16.h>
#include <cstdint>

// ---------------------------------------------------------------------------
// TransformerConv: N=100000 nodes, E=1600000 edges, IN=128, H=4, C=32, ED=16
//
// sm_103 base target (NO tcgen05 — harness PTX is .target sm_103):
//   1) pack_w     : W{q,k,v,skip} -> fp16, transposed [512 x 128]
//   2) fold_zero  : Wg = fold(Wq, We) -> rows 512..575; zero d_count
//   3) fill_buckets: bucket {edge,src} pairs by destination node
//   4) proj_mma   : single fp16 mma.sync (x_h * W_h), fp32 accum,
//                   M=256 tile / 512 threads; compile-time-NF inner loops,
//                   B fragments via ldmatrix.x4 (2 n-tiles per LDSM)
//   5) agg_kernel : warp-per-dst-node, batched-shfl + prefetch-4 gathers,
//                   softmax aggregation + gated skip fused
// ---------------------------------------------------------------------------

#define MAXN 100096
#define BCAP 96   // per-node bucket capacity (Poisson(16) max ~36; 96 is safe)

__device__ float d_qbuf[MAXN * 128];
__device__ float d_sbuf[MAXN * 128];
__device__ float d_gbuf[MAXN * 64];
__device__ uint4 d_kv[MAXN * 32];      // per node: 32 lanes x 16B {k4 half, v4 half}
__device__ int   d_count[MAXN];
__device__ int2  d_bucket[MAXN * BCAP];   // {edge id, src node}
__device__ __half d_B[576 * 128];      // W^T fp16, n-major rows, k cols (+Wg)
__device__ float d_bg[64];             // bias for folded g projection

// ============================ helpers ======================================
__device__ __forceinline__ uint32_t smem_u32(const void* p) {
    uint32_t a;
    asm("{ .reg .u64 t; cvta.to.shared.u64 t, %1; cvt.u32.u64 %0, t; }"
        : "=r"(a) : "l"(p));
    return a;
}
__device__ __forceinline__ void ldm_x4(uint32_t& r0, uint32_t& r1,
                                       uint32_t& r2, uint32_t& r3, uint32_t addr) {
    asm volatile("ldmatrix.sync.aligned.m8n8.x4.shared.b16 {%0,%1,%2,%3}, [%4];"
                 : "=r"(r0), "=r"(r1), "=r"(r2), "=r"(r3) : "r"(addr));
}
__device__ __forceinline__ void mma_f16(float* c, const uint32_t* a,
                                        uint32_t b0, uint32_t b1) {
    asm volatile(
        "mma.sync.aligned.m16n8k16.row.col.f32.f16.f16.f32 "
        "{%0,%1,%2,%3}, {%4,%5,%6,%7}, {%8,%9}, {%0,%1,%2,%3};"
        : "+f"(c[0]), "+f"(c[1]), "+f"(c[2]), "+f"(c[3])
        : "r"(a[0]), "r"(a[1]), "r"(a[2]), "r"(a[3]), "r"(b0), "r"(b1));
}

// ---------------------------------------------------------------------------
// pack_w: W[k][col] (4 matrices) -> d_B[n=512 rows][k=128] fp16
// ---------------------------------------------------------------------------
__global__ void __launch_bounds__(256)
pack_w(const float* __restrict__ Wq, const float* __restrict__ Wk,
       const float* __restrict__ Wv, const float* __restrict__ Ws)
{
    int i = blockIdx.x * 256 + threadIdx.x;   // 65536 elements
    int k = i >> 9, nn = i & 511;
    int w = nn >> 7, c = nn & 127;
    const float* W = (w == 0) ? Wq : (w == 1) ? Wk : (w == 2) ? Wv : Ws;
    d_B[nn * 128 + k] = __float2half_rn(W[k * 128 + c]);
}

// ---------------------------------------------------------------------------
// fold_zero: blocks [0,32): Wg fold; [32, ...): zero d_count
// ---------------------------------------------------------------------------
__global__ void __launch_bounds__(256)
fold_zero(const float* __restrict__ Wq, const float* __restrict__ We,
          const float* __restrict__ bq)
{
    int b = blockIdx.x, tid = threadIdx.x;
    if (b < 32) {
        int t = b * 256 + tid;               // 8192: (i, o)
        int i = t >> 6, o = t & 63;
        int h = o >> 4, d = o & 15;
        float s = 0.f;
#pragma unroll
        for (int c = 0; c < 32; ++c)
            s += Wq[i * 128 + h * 32 + c] * We[d * 128 + h * 32 + c];
        d_B[(512 + o) * 128 + i] = __float2half_rn(s);
        if (i == 0) {
            float sb = 0.f;
#pragma unroll
            for (int c = 0; c < 32; ++c)
                sb += bq[h * 32 + c] * We[d * 128 + h * 32 + c];
            d_bg[o] = sb;
        }
    } else {
        int i = (b - 32) * 256 + tid;
        if (i < MAXN) d_count[i] = 0;
    }
}

// ---------------------------------------------------------------------------
// Edge bucketing: store {edge, src} pairs (kills a dependent load in agg)
// ---------------------------------------------------------------------------
__global__ void __launch_bounds__(256)
fill_buckets(const int* __restrict__ row, const int* __restrict__ colv, int e)
{
    int i = blockIdx.x * blockDim.x + threadIdx.x;
    if (i >= e) return;
    int dst = row[i];
    int src = colv[i];
    int pos = atomicAdd(&d_count[dst], 1);
    if (pos < BCAP) d_bucket[dst * BCAP + pos] = make_int2(i, src);
}

// ---------------------------------------------------------------------------
// Projection via single fp16 mma.sync: per CTA M=256 tile / 512 threads,
// 5 N-chunks (q,k,v,skip,g). smem rows padded to 136 halves -> conflict-free.
// ---------------------------------------------------------------------------
#define ASTR 136
#define PROJ_SMEM ((256 + 128) * ASTR * 2)

// Compile-time NF inner loop: full unroll, B via ldmatrix.x4 (2 n-tiles/LDSM).
template <int NF>
__device__ __forceinline__ void mma_chunk(uint32_t uA, uint32_t uB,
                                          float (*acc)[4], int wid, int lane)
{
    uint32_t a_row = (uint32_t)(wid * 16 + (lane & 15));
    uint32_t a_koff = (uint32_t)((lane >> 4) * 8);
    // B x4 lane mapping: lanes [0,16) -> even n-tile, [16,32) -> odd n-tile;
    // within each half, (lane>>3)&1 selects k-lo / k-hi 8x8 matrix.
    uint32_t b_sub = (uint32_t)((lane >> 4) & 1);      // even/odd n-tile
    uint32_t b_kh  = (uint32_t)((lane >> 3) & 1);      // k-halves
    uint32_t b_rin = (uint32_t)(lane & 7);
#pragma unroll
    for (int ks = 0; ks < 8; ++ks) {
        uint32_t a[4];
        ldm_x4(a[0], a[1], a[2], a[3],
               uA + (a_row * ASTR + ks * 16 + a_koff) * 2);
#pragma unroll
        for (int p = 0; p < NF / 2; ++p) {
            uint32_t brow = (2 * p + b_sub) * 8 + b_rin;
            uint32_t b0, b1, b2, b3;
            ldm_x4(b0, b1, b2, b3,
                   uB + (brow * ASTR + ks * 16 + b_kh * 8) * 2);
            mma_f16(acc[2 * p], a, b0, b1);
            mma_f16(acc[2 * p + 1], a, b2, b3);
        }
    }
}

__global__ void __launch_bounds__(512, 1)
proj_mma(const float* __restrict__ x,
         const float* __restrict__ bq, const float* __restrict__ bk,
         const float* __restrict__ bv, const float* __restrict__ bs,
         int n)
{
    extern __shared__ __align__(16) char smem[];
    ushort* sA = (ushort*)smem;                 // [256][ASTR]
    ushort* sB = sA + 256 * ASTR;               // [128][ASTR]

    int tid = threadIdx.x, lane = tid & 31, wid = tid >> 5;
    int row0 = blockIdx.x * 256;

    // Stage x tile -> fp16
    for (int i = tid; i < 256 * 32; i += 512) {
        int r = i >> 5, c4 = i & 31;
        int node = row0 + r;
        float4 xv = (node < n) ? *(const float4*)&x[node * 128 + c4 * 4]
                               : make_float4(0.f, 0.f, 0.f, 0.f);
        __half2 h01 = __floats2half2_rn(xv.x, xv.y);
        __half2 h23 = __floats2half2_rn(xv.z, xv.w);
        *(uint2*)&sA[r * ASTR + c4 * 4] =
            make_uint2(*(uint32_t*)&h01, *(uint32_t*)&h23);
    }

    uint32_t uA = smem_u32(sA);
    uint32_t uB = smem_u32(sB);

    const float* biasl[4] = {bq, bk, bv, bs};
    ushort* kvs = (ushort*)d_kv;

    for (int nc = 0; nc < 5; ++nc) {
        int NF = (nc == 4) ? 8 : 16;             // g chunk is N=64
        __syncthreads();
        // Stage W chunk [NF*8 n-rows][128 k]
        for (int i = tid; i < NF * 8 * 16; i += 512) {
            int r = i >> 4, c8 = i & 15;
            *(uint4*)&sB[r * ASTR + c8 * 8] =
                *(const uint4*)&d_B[(nc * 128 + r) * 128 + c8 * 8];
        }
        __syncthreads();

        float acc[16][4];
#pragma unroll
        for (int f = 0; f < 16; ++f)
#pragma unroll
            for (int j = 0; j < 4; ++j) acc[f][j] = 0.f;

        if (nc == 4) mma_chunk<8>(uA, uB, acc, wid, lane);
        else         mma_chunk<16>(uA, uB, acc, wid, lane);

        // Epilogue
        int r_base = row0 + wid * 16 + (lane >> 2);
        if (nc == 4) {
#pragma unroll
            for (int nf = 0; nf < 8; ++nf) {
                int cn = nf * 8 + (lane & 3) * 2;
                float b0 = d_bg[cn], b1 = d_bg[cn + 1];
#pragma unroll
                for (int half = 0; half < 2; ++half) {
                    int node = r_base + half * 8;
                    if (node >= n) continue;
                    *(float2*)&d_gbuf[node * 64 + cn] =
                        make_float2(acc[nf][half * 2] + b0, acc[nf][half * 2 + 1] + b1);
                }
            }
        } else {
            const float* bias = biasl[nc];
#pragma unroll
            for (int nf = 0; nf < 16; ++nf) {
                int cn = nf * 8 + (lane & 3) * 2;
                float b0 = __ldg(&bias[cn]), b1 = __ldg(&bias[cn + 1]);
#pragma unroll
                for (int half = 0; half < 2; ++half) {
                    int node = r_base + half * 8;
                    if (node >= n) continue;
                    float v0 = acc[nf][half * 2 + 0] + b0;
                    float v1 = acc[nf][half * 2 + 1] + b1;
                    if (nc == 0) {
                        *(float2*)&d_qbuf[node * 128 + cn] = make_float2(v0, v1);
                    } else if (nc == 3) {
                        *(float2*)&d_sbuf[node * 128 + cn] = make_float2(v0, v1);
                    } else {
                        __half2 hh = __floats2half2_rn(v0, v1);
                        uint32_t idx = (uint32_t)node * 256 + ((cn >> 2) << 3)
                                     + (cn & 3) + (nc == 2 ? 4 : 0);
                        *(uint32_t*)&kvs[idx] = *(uint32_t*)&hh;
                    }
                }
            }
        }
    }
}

// ---------------------------------------------------------------------------
// Warp-per-node softmax aggregation + gated skip.
// Batched {edge,src} preload (coalesced) + shfl broadcast + prefetch-4.
// ---------------------------------------------------------------------------
__global__ void __launch_bounds__(256)
agg_kernel(const float* __restrict__ edge_attr,
           const float* __restrict__ Wbeta,
           float* __restrict__ out, int n)
{
    int warp = (blockIdx.x * blockDim.x + threadIdx.x) >> 5;
    int lane = threadIdx.x & 31;
    if (warp >= n) return;
    int node = warp;
    int l8 = lane & 7;
    int h = lane >> 3;

    float4 q4 = *(const float4*)&d_qbuf[node * 128 + lane * 4];
    float2 g2 = *(const float2*)&d_gbuf[node * 64 + h * 16 + l8 * 2];

    int deg = d_count[node];
    if (deg > BCAP) deg = BCAP;

    float4 acc = make_float4(0.f, 0.f, 0.f, 0.f);
    float den = 0.f;

    for (int j0 = 0; j0 < deg; j0 += 32) {
        int jb = min(32, deg - j0);
        int e_l = 0, s_l = 0;
        if (lane < jb) {
            int2 es = d_bucket[node * BCAP + j0 + lane];
            e_l = es.x; s_l = es.y;
        }
        int j = 0;
        for (; j + 4 <= jb; j += 4) {
            uint4 kvv[4];
            float2 ea[4];
#pragma unroll
            for (int t = 0; t < 4; ++t) {
                int e   = __shfl_sync(0xffffffffu, e_l, j + t);
                int src = __shfl_sync(0xffffffffu, s_l, j + t);
                kvv[t] = __ldg(&d_kv[src * 32 + lane]);
                ea[t]  = *(const float2*)&edge_attr[e * 16 + l8 * 2];
            }
#pragma unroll
            for (int t = 0; t < 4; ++t) {
                float2 k01 = __half22float2(*(__half2*)&kvv[t].x);
                float2 k23 = __half22float2(*(__half2*)&kvv[t].y);
                float2 v01 = __half22float2(*(__half2*)&kvv[t].z);
                float2 v23 = __half22float2(*(__half2*)&kvv[t].w);
                float dot = q4.x * k01.x + q4.y * k01.y + q4.z * k23.x + q4.w * k23.y
                          + g2.x * ea[t].x + g2.y * ea[t].y;
                dot += __shfl_xor_sync(0xffffffffu, dot, 1);
                dot += __shfl_xor_sync(0xffffffffu, dot, 2);
                dot += __shfl_xor_sync(0xffffffffu, dot, 4);
                float ex = __expf(dot * 0.17677669529663687f);  // 1/sqrt(32)
                den += ex;
                acc.x += ex * v01.x; acc.y += ex * v01.y;
                acc.z += ex * v23.x; acc.w += ex * v23.y;
            }
        }
        for (; j < jb; ++j) {
            int e   = __shfl_sync(0xffffffffu, e_l, j);
            int src = __shfl_sync(0xffffffffu, s_l, j);
            uint4 kvv = __ldg(&d_kv[src * 32 + lane]);
            float2 ea = *(const float2*)&edge_attr[e * 16 + l8 * 2];
            float2 k01 = __half22float2(*(__half2*)&kvv.x);
            float2 k23 = __half22float2(*(__half2*)&kvv.y);
            float2 v01 = __half22float2(*(__half2*)&kvv.z);
            float2 v23 = __half22float2(*(__half2*)&kvv.w);
            float dot = q4.x * k01.x + q4.y * k01.y + q4.z * k23.x + q4.w * k23.y
                      + g2.x * ea.x + g2.y * ea.y;
            dot += __shfl_xor_sync(0xffffffffu, dot, 1);
            dot += __shfl_xor_sync(0xffffffffu, dot, 2);
            dot += __shfl_xor_sync(0xffffffffu, dot, 4);
            float ex = __expf(dot * 0.17677669529663687f);
            den += ex;
            acc.x += ex * v01.x; acc.y += ex * v01.y;
            acc.z += ex * v23.x; acc.w += ex * v23.y;
        }
    }

    float inv = 1.f / (den + 1e-16f);
    float4 o4 = make_float4(acc.x * inv, acc.y * inv, acc.z * inv, acc.w * inv);
    float4 xs4 = *(const float4*)&d_sbuf[node * 128 + lane * 4];

    // beta = sigmoid(out.(Wb0+Wb2) + xs.(Wb1-Wb2))
    float4 wb0 = *(const float4*)&Wbeta[lane * 4];
    float4 wb1 = *(const float4*)&Wbeta[128 + lane * 4];
    float4 wb2 = *(const float4*)&Wbeta[256 + lane * 4];
    float s = o4.x * (wb0.x + wb2.x) + o4.y * (wb0.y + wb2.y)
            + o4.z * (wb0.z + wb2.z) + o4.w * (wb0.w + wb2.w)
            + xs4.x * (wb1.x - wb2.x) + xs4.y * (wb1.y - wb2.y)
            + xs4.z * (wb1.z - wb2.z) + xs4.w * (wb1.w - wb2.w);
    s += __shfl_xor_sync(0xffffffffu, s, 1);
    s += __shfl_xor_sync(0xffffffffu, s, 2);
    s += __shfl_xor_sync(0xffffffffu, s, 4);
    s += __shfl_xor_sync(0xffffffffu, s, 8);
    s += __shfl_xor_sync(0xffffffffu, s, 16);
    float beta = 1.f / (1.f + __expf(-s));

    float4 r;
    r.x = beta * xs4.x + (1.f - beta) * o4.x;
    r.y = beta * xs4.y + (1.f - beta) * o4.y;
    r.z = beta * xs4.z + (1.f - beta) * o4.z;
    r.w = beta * xs4.w + (1.f - beta) * o4.w;
    *(float4*)&out[node * 128 + lane * 4] = r;
}

// ---------------------------------------------------------------------------
extern "C" void kernel_launch(void* const* d_in, const int* in_sizes, int n_in,
                              void* d_out, int out_size)
{
    const float* x         = (const float*)d_in[0];
    const float* edge_attr = (const float*)d_in[1];
    const int*   edge_idx  = (const int*)  d_in[2];
    const float* Wq = (const float*)d_in[3];
    const float* bq = (const float*)d_in[4];
    const float* Wk = (const float*)d_in[5];
    const float* bk = (const float*)d_in[6];
    const float* Wv = (const float*)d_in[7];
    const float* bv = (const float*)d_in[8];
    const float* We = (const float*)d_in[9];
    const float* Ws = (const float*)d_in[10];
    const float* bs = (const float*)d_in[11];
    const float* Wbeta = (const float*)d_in[12];
    float* out = (float*)d_out;

    int n = in_sizes[0] / 128;
    int e = in_sizes[1] / 16;
    const int* row  = edge_idx;      // destination nodes
    const int* colv = edge_idx + e;  // source nodes

    cudaFuncSetAttribute(proj_mma, cudaFuncAttributeMaxDynamicSharedMemorySize,
                         PROJ_SMEM);

    pack_w<<<256, 256>>>(Wq, Wk, Wv, Ws);
    fold_zero<<<32 + (MAXN + 255) / 256, 256>>>(Wq, We, bq);
    fill_buckets<<<(e + 255) / 256, 256>>>(row, colv, e);
    proj_mma<<<(n + 255) / 256, 512, PROJ_SMEM>>>(x, bq, bk, bv, bs, n);
    agg_kernel<<<((long long)n * 32 + 255) / 256, 256>>>(edge_attr, Wbeta, out, n);
}